// round 14
// baseline (speedup 1.0000x reference)
#include <cuda_runtime.h>
#include <cuda_fp16.h>
#include <math.h>
#include <cstdint>

// Problem constants
#define Bq   8
#define Lq   1024
#define Dq   1024
#define Nq   32
#define Mq   (Bq * Lq)          // 8192 rows

#define BM 128
#define BN 128
#define BK 64
#define STAGES 3

// ---------------- scratch (device globals; no allocations allowed) ----------
__device__ __align__(128) __half g_xh [(size_t)Mq * Dq];       // x fp16
__device__ __align__(128) __half g_ut [(size_t)Mq * Dq];       // in_proj out (B, D, L)
__device__ __align__(128) __half g_yt [(size_t)Mq * Dq];       // SSM out (B, D, L)
__device__ __align__(128) __half g_ygh[(size_t)Mq * Dq];       // GLU out fp16
__device__ __align__(128) __half g_wih[(size_t)Dq * Dq];       // in_W fp16
__device__ __align__(128) __half g_wgh[(size_t)2 * Dq * Dq];   // glu_W fp16
__device__ __align__(128) __half g_woh[(size_t)Dq * Dq];       // out_W fp16

// ==================== PTX helpers (baseline sm_80+ features only) ===========
__device__ __forceinline__ uint32_t smem_u32(const void* p) {
    return (uint32_t)__cvta_generic_to_shared(p);
}
__device__ __forceinline__ void cp_async16(uint32_t dst, const void* src) {
    asm volatile("cp.async.cg.shared.global [%0], [%1], 16;" :: "r"(dst), "l"(src));
}
__device__ __forceinline__ void cp_async16_ca(uint32_t dst, const void* src) {
    asm volatile("cp.async.ca.shared.global [%0], [%1], 16;" :: "r"(dst), "l"(src));
}
__device__ __forceinline__ void cp_commit() {
    asm volatile("cp.async.commit_group;" ::: "memory");
}
template <int N>
__device__ __forceinline__ void cp_wait() {
    asm volatile("cp.async.wait_group %0;" :: "n"(N) : "memory");
}
__device__ __forceinline__ void ldsm_x4(uint32_t* r, uint32_t addr) {
    asm volatile("ldmatrix.sync.aligned.m8n8.x4.shared.b16 {%0,%1,%2,%3}, [%4];"
                 : "=r"(r[0]), "=r"(r[1]), "=r"(r[2]), "=r"(r[3]) : "r"(addr));
}
__device__ __forceinline__ void ldsm_x4_trans(uint32_t* r, uint32_t addr) {
    asm volatile("ldmatrix.sync.aligned.m8n8.x4.trans.shared.b16 {%0,%1,%2,%3}, [%4];"
                 : "=r"(r[0]), "=r"(r[1]), "=r"(r[2]), "=r"(r[3]) : "r"(addr));
}
__device__ __forceinline__ void mma16816(float* c, const uint32_t* a, uint32_t b0, uint32_t b1) {
    asm volatile("mma.sync.aligned.m16n8k16.row.col.f32.f16.f16.f32 "
                 "{%0,%1,%2,%3}, {%4,%5,%6,%7}, {%8,%9}, {%0,%1,%2,%3};"
                 : "+f"(c[0]), "+f"(c[1]), "+f"(c[2]), "+f"(c[3])
                 : "r"(a[0]), "r"(a[1]), "r"(a[2]), "r"(a[3]), "r"(b0), "r"(b1));
}

// ---------------- fp32 -> fp16 conversion (all tensors in one launch) -------
#define N4X (Mq * Dq / 4)
#define N4I (Dq * Dq / 4)
#define N4G (2 * Dq * Dq / 4)
#define N4O (Dq * Dq / 4)
__global__ void cvt_all_kernel(const float* __restrict__ x,
                               const float* __restrict__ wi,
                               const float* __restrict__ wg,
                               const float* __restrict__ wo,
                               __half* __restrict__ xh, __half* __restrict__ wih,
                               __half* __restrict__ wgh, __half* __restrict__ woh) {
    int i = blockIdx.x * blockDim.x + threadIdx.x;
    const float* src;
    __half* dst;
    int j = i;
    if (j < N4X) { src = x; dst = xh; }
    else if ((j -= N4X) < N4I) { src = wi; dst = wih; }
    else if ((j -= N4I) < N4G) { src = wg; dst = wgh; }
    else if ((j -= N4G) < N4O) { src = wo; dst = woh; }
    else return;
    float4 v = ((const float4*)src)[j];
    __half2 h0 = __floats2half2_rn(v.x, v.y);
    __half2 h1 = __floats2half2_rn(v.z, v.w);
    uint2 o;
    o.x = *(uint32_t*)&h0;
    o.y = *(uint32_t*)&h1;
    ((uint2*)dst)[j] = o;
}

// ==================== HMMA fp16 GEMM (main projections) =====================
__device__ __forceinline__ void gemm_load_stage(uint32_t base, const __half* as,
                                                const __half* ws, int K, int tid) {
#pragma unroll
    for (int i = 0; i < 4; ++i) {
        int idx = i * 256 + tid;
        int row = idx >> 3, c = idx & 7;
        uint32_t off = (uint32_t)(row * 128 + ((c * 16) ^ ((row & 7) << 4)));
        cp_async16(base + off, as + (size_t)row * K + c * 8);
    }
    const uint32_t stA = BM * BK * 2;
#pragma unroll
    for (int i = 0; i < 4; ++i) {
        int idx = i * 256 + tid;
        int row = idx >> 3, c = idx & 7;
        uint32_t off = (uint32_t)(row * 128 + ((c * 16) ^ ((row & 7) << 4)));
        cp_async16_ca(base + stA + off, ws + (size_t)row * K + c * 8);
    }
}

// EPI: 1 = fp32 out + bias(col) + fp16 residual, row-major C (M x Nn)
//      4 = fp16 out + bias(row),  C written as (B, D, L): row = d, col = m
template <int EPI>
__global__ void __launch_bounds__(256)
hgemm_kernel(const __half* __restrict__ A, const __half* __restrict__ W,
             const float* __restrict__ bias, const __half* __restrict__ Rh,
             void* __restrict__ Cv, int M, int Nn, int K) {
    extern __shared__ __align__(1024) char smem[];
    const uint32_t sb = smem_u32(smem);
    const int tid = threadIdx.x;
    const int lane = tid & 31;
    const int wid = tid >> 5;
    const int wm = (wid & 3) * 32;
    const int wn = (wid >> 2) * 64;
    const int bx = blockIdx.x, by = blockIdx.y;

    const uint32_t stA = BM * BK * 2;
    const uint32_t stage_sz = 2 * stA;
    const int nk = K / BK;

    const __half* Ab = A + (size_t)(by * BM) * K;
    const __half* Wb = W + (size_t)(bx * BN) * K;

    gemm_load_stage(sb + 0 * stage_sz, Ab, Wb, K, tid);
    cp_commit();
    gemm_load_stage(sb + 1 * stage_sz, Ab + BK, Wb + BK, K, tid);
    cp_commit();

    float acc[2][8][4];
#pragma unroll
    for (int i = 0; i < 2; ++i)
#pragma unroll
        for (int j = 0; j < 8; ++j)
#pragma unroll
            for (int l = 0; l < 4; ++l) acc[i][j][l] = 0.0f;

    const int a_r  = lane & 15;
    const int a_kb = (lane >> 4) * 16;
    const int b_r  = ((lane >> 4) * 8) + (lane & 7);
    const int b_kb = ((lane >> 3) & 1) * 16;

    for (int kt = 0; kt < nk; ++kt) {
        cp_wait<STAGES - 2>();
        __syncthreads();

        if (kt + 2 < nk) {
            gemm_load_stage(sb + ((kt + 2) % STAGES) * stage_sz,
                            Ab + (kt + 2) * BK, Wb + (kt + 2) * BK, K, tid);
        }
        cp_commit();

        const uint32_t baseA = sb + (kt % STAGES) * stage_sz;
        const uint32_t baseB = baseA + stA;

#pragma unroll
        for (int ks = 0; ks < 4; ++ks) {
            const int kb0 = ks * 32;
            uint32_t a_frag[2][4];
#pragma unroll
            for (int mt = 0; mt < 2; ++mt) {
                int row = wm + mt * 16 + a_r;
                uint32_t addr = baseA + row * 128 + ((kb0 + a_kb) ^ ((row & 7) << 4));
                ldsm_x4(a_frag[mt], addr);
            }
            uint32_t b_frag[4][4];
#pragma unroll
            for (int nb4 = 0; nb4 < 4; ++nb4) {
                int row = wn + nb4 * 16 + b_r;
                uint32_t addr = baseB + row * 128 + ((kb0 + b_kb) ^ ((row & 7) << 4));
                ldsm_x4(b_frag[nb4], addr);
            }
#pragma unroll
            for (int mt = 0; mt < 2; ++mt)
#pragma unroll
                for (int nb = 0; nb < 8; ++nb) {
                    uint32_t b0 = b_frag[nb >> 1][(nb & 1) * 2 + 0];
                    uint32_t b1 = b_frag[nb >> 1][(nb & 1) * 2 + 1];
                    mma16816(acc[mt][nb], a_frag[mt], b0, b1);
                }
        }
    }

    const int gr = lane >> 2;
    const int gc = (lane & 3) * 2;

    if (EPI == 1) {
        float* C = (float*)Cv;
#pragma unroll
        for (int mt = 0; mt < 2; ++mt) {
#pragma unroll
            for (int nb = 0; nb < 8; ++nb) {
                int row0 = by * BM + wm + mt * 16 + gr;
                int col  = bx * BN + wn + nb * 8 + gc;
                float2 bs = *(const float2*)&bias[col];
                float2 v0, v1;
                v0.x = acc[mt][nb][0] + bs.x;
                v0.y = acc[mt][nb][1] + bs.y;
                v1.x = acc[mt][nb][2] + bs.x;
                v1.y = acc[mt][nb][3] + bs.y;
                __half2 r0 = *(const __half2*)&Rh[(size_t)row0 * Nn + col];
                __half2 r1 = *(const __half2*)&Rh[(size_t)(row0 + 8) * Nn + col];
                v0.x += __low2float(r0); v0.y += __high2float(r0);
                v1.x += __low2float(r1); v1.y += __high2float(r1);
                *(float2*)&C[(size_t)row0 * Nn + col] = v0;
                *(float2*)&C[(size_t)(row0 + 8) * Nn + col] = v1;
            }
        }
    } else {
        // EPI == 4: rows = channels d, cols = m (one batch per tile).
        __half* C = (__half*)Cv;
        const int b  = (bx * BN) / Lq;
        const int l0 = (bx * BN) % Lq;
#pragma unroll
        for (int mt = 0; mt < 2; ++mt) {
            int d0 = by * BM + wm + mt * 16 + gr;
            float bs0 = bias[d0];
            float bs1 = bias[d0 + 8];
            __half* r0p = C + ((size_t)(b * Dq + d0)) * Lq + l0;
            __half* r1p = C + ((size_t)(b * Dq + d0 + 8)) * Lq + l0;
#pragma unroll
            for (int nb = 0; nb < 8; ++nb) {
                int cl = wn + nb * 8 + gc;
                *(__half2*)&r0p[cl] = __floats2half2_rn(acc[mt][nb][0] + bs0,
                                                        acc[mt][nb][1] + bs0);
                *(__half2*)&r1p[cl] = __floats2half2_rn(acc[mt][nb][2] + bs1,
                                                        acc[mt][nb][3] + bs1);
            }
        }
    }
}

// ==================== chunked SSM kernel (prep fused in) =====================
#define SM_KT  0
#define SM_P   8192
#define SM_SO  16384
#define SM_U   24576
#define SM_SH  40960
#define SM_AGG 57344
#define SM_WT  74240
#define SM_KS  74496
#define AGG_STRIDE 132
#define SM_TOTAL_S4 74752

__device__ __forceinline__ void small_gemm(uint32_t Abase, uint32_t Bbase,
                                           float acc[8][4], int wmi, int wn, int lane) {
    const int a_r  = lane & 15;
    const int a_kb = (lane >> 4) * 16;
    const int b_r  = ((lane >> 4) * 8) + (lane & 7);
    const int b_kb = ((lane >> 3) & 1) * 16;
#pragma unroll
    for (int ks = 0; ks < 4; ++ks) {
        const int kb0 = ks * 32;
        uint32_t a_frag[4];
        {
            int row = wmi + a_r;
            ldsm_x4(a_frag, Abase + row * 128 + ((kb0 + a_kb) ^ ((row & 7) << 4)));
        }
        uint32_t b_frag[4][4];
#pragma unroll
        for (int nb4 = 0; nb4 < 4; ++nb4) {
            int row = wn + nb4 * 16 + b_r;
            ldsm_x4(b_frag[nb4], Bbase + row * 128 + ((kb0 + b_kb) ^ ((row & 7) << 4)));
        }
#pragma unroll
        for (int nb = 0; nb < 8; ++nb)
            mma16816(acc[nb], a_frag,
                     b_frag[nb >> 1][(nb & 1) * 2 + 0],
                     b_frag[nb >> 1][(nb & 1) * 2 + 1]);
    }
}

// half store at swizzled (row, col) in a 128B-row tile
__device__ __forceinline__ void st_sw(char* smem, uint32_t base, int row, int col, float v) {
    *(__half*)(smem + base + row * 128 + ((col * 2) ^ ((row & 7) << 4))) = __float2half(v);
}

__global__ void __launch_bounds__(256, 3)
s4chunk_kernel(const __half* __restrict__ Ut,
               const float* __restrict__ log_dt, const float* __restrict__ Cc,
               const float* __restrict__ log_A_real, const float* __restrict__ A_imag,
               const float* __restrict__ dskip, __half* __restrict__ Yt) {
    extern __shared__ __align__(1024) char smem[];
    const uint32_t sb = smem_u32(smem);
    const int d = blockIdx.x;
    const int tid = threadIdx.x;
    const int lane = tid & 31;
    const int wid = tid >> 5;
    const int wmi = (wid & 3) * 16;
    const int wn  = (wid >> 2) * 64;

    __half* AGG16 = (__half*)(smem + SM_AGG);   // [64][132] fp16
    __half* Ysm   = (__half*)(smem + SM_AGG);   // reused: [128][64] fp16
    float*  WT    = (float*)(smem + SM_WT);     // [32][2]
    float*  KS    = (float*)(smem + SM_KS);     // [64]

    // ---- kick off U tile load first (overlaps prep math) ----
#pragma unroll
    for (int i = 0; i < 4; ++i) {
        int e = i * 256 + tid;
        int row = e >> 3, c8 = e & 7;
        int b = row >> 4, cl = row & 15;
        uint32_t off = row * 128 + ((c8 * 16) ^ ((row & 7) << 4));
        cp_async16(sb + SM_U + off,
                   Ut + ((size_t)(b * Dq + d)) * Lq + cl * 64 + c8 * 8);
    }
    cp_commit();

    // ---- fused prep: each warp computes 8 powers (p0 = wid*8) ----
    {
        const int n = lane;
        const int idx = d * Nq + n;
        float dt   = expf(log_dt[d]);
        float a_re = -expf(log_A_real[idx]);
        float a_im = A_imag[idx];
        float ex   = expf(a_re * dt);
        float wre  = ex * cosf(a_im * dt);
        float wim  = ex * sinf(a_im * dt);
        float n_re = wre - 1.0f, n_im = wim;
        float den  = a_re * a_re + a_im * a_im;
        float f_re = (n_re * a_re + n_im * a_im) / den;
        float f_im = (n_im * a_re - n_re * a_im) / den;
        float C_re = Cc[idx * 2 + 0];
        float C_im = Cc[idx * 2 + 1];
        float cre  = 2.0f * (C_re * f_re - C_im * f_im);
        float cim  = 2.0f * (C_re * f_im + C_im * f_re);

        // w^(p0) via binary exponentiation
        int e = wid * 8;
        float pr = 1.0f, pi = 0.0f, br = wre, bi = wim;
        while (e) {
            if (e & 1) {
                float t = pr * br - pi * bi;
                pi = pr * bi + pi * br;
                pr = t;
            }
            float t2 = br * br - bi * bi;
            bi = 2.0f * br * bi;
            br = t2;
            e >>= 1;
        }
        float qr = cre * pr - cim * pi;
        float qi = cre * pi + cim * pr;

#pragma unroll
        for (int j = 0; j < 8; ++j) {
            int p = wid * 8 + j;
            st_sw(smem, SM_P, n, 63 - p, pr);
            st_sw(smem, SM_P, 32 + n, 63 - p, pi);
            float s = qr;
#pragma unroll
            for (int off = 16; off; off >>= 1)
                s += __shfl_xor_sync(0xffffffffu, s, off);
            if (n == 0) KS[p] = s;
            if (p >= 1) {
                st_sw(smem, SM_SO, p - 1, n, qr);
                st_sw(smem, SM_SO, p - 1, 32 + n, -qi);
            }
            float npr = pr * wre - pi * wim;
            float npi = pr * wim + pi * wre;
            pr = npr; pi = npi;
            float nqr = qr * wre - qi * wim;
            float nqi = qr * wim + qi * wre;
            qr = nqr; qi = nqi;
        }
        if (wid == 7) {
            st_sw(smem, SM_SO, 63, n, qr);
            st_sw(smem, SM_SO, 63, 32 + n, -qi);
            WT[n * 2 + 0] = pr;
            WT[n * 2 + 1] = pi;
        }
    }
    __syncthreads();

    // ---- KT fill: KT[i][j] = k[i-j] (j<=i) + skip on diagonal ----
    {
        const float skip = dskip[d];
        for (int ee = tid; ee < 4096; ee += 256) {
            int i = ee >> 6, j = ee & 63;
            float v = (j <= i ? KS[i - j] : 0.0f) + (i == j ? skip : 0.0f);
            st_sw(smem, SM_KT, i, j, v);
        }
    }
    cp_wait<0>();
    __syncthreads();

    const int gr = lane >> 2;
    const int gc = (lane & 3) * 2;

    // GEMM1: AGG = P @ U^T  (fp16 staging, padded stride)
    {
        float agg[8][4];
#pragma unroll
        for (int j = 0; j < 8; ++j)
#pragma unroll
            for (int l = 0; l < 4; ++l) agg[j][l] = 0.0f;
        small_gemm(sb + SM_P, sb + SM_U, agg, wmi, wn, lane);
#pragma unroll
        for (int nb = 0; nb < 8; ++nb) {
            int col = wn + nb * 8 + gc;
            *(__half2*)&AGG16[(wmi + gr) * AGG_STRIDE + col] =
                __floats2half2_rn(agg[nb][0], agg[nb][1]);
            *(__half2*)&AGG16[(wmi + gr + 8) * AGG_STRIDE + col] =
                __floats2half2_rn(agg[nb][2], agg[nb][3]);
        }
    }
    __syncthreads();

    // boundary-state recurrence (fp32 state, fp16 AGG reads)
    {
        int n = tid & 31, b = tid >> 5;
        float wtr = WT[n * 2 + 0];
        float wti = WT[n * 2 + 1];
        float Er = 0.0f, Ei = 0.0f;
        for (int cl = 0; cl < 16; ++cl) {
            int c = b * 16 + cl;
            *(__half*)(smem + SM_SH + c * 128 + ((n * 2) ^ ((c & 7) << 4))) = __float2half(Er);
            *(__half*)(smem + SM_SH + c * 128 + (((32 + n) * 2) ^ ((c & 7) << 4))) = __float2half(Ei);
            float ar = __half2float(AGG16[n * AGG_STRIDE + c]);
            float ai = __half2float(AGG16[(32 + n) * AGG_STRIDE + c]);
            float nEr = fmaf(wtr, Er, fmaf(-wti, Ei, ar));
            float nEi = fmaf(wtr, Ei, fmaf(wti, Er, ai));
            Er = nEr; Ei = nEi;
        }
    }
    __syncthreads();

    // GEMM2 + GEMM3: Y = KT @ U^T + SO @ S_h
    float acc[8][4];
#pragma unroll
    for (int j = 0; j < 8; ++j)
#pragma unroll
        for (int l = 0; l < 4; ++l) acc[j][l] = 0.0f;
    small_gemm(sb + SM_KT, sb + SM_U,  acc, wmi, wn, lane);
    small_gemm(sb + SM_SO, sb + SM_SH, acc, wmi, wn, lane);

    // GELU directly on accumulator, stage to Ysm
#pragma unroll
    for (int nb = 0; nb < 8; ++nb) {
#pragma unroll
        for (int q = 0; q < 4; ++q) {
            int i = wmi + gr + (q >> 1) * 8;
            int c = wn + nb * 8 + gc + (q & 1);
            float v = acc[nb][q];
            float g = 0.5f * v * (1.0f + erff(v * 0.70710678118654752f));
            Ysm[c * 64 + i] = __float2half(g);
        }
    }
    __syncthreads();

#pragma unroll
    for (int it = 0; it < 16; ++it) {
        int e2 = it * 256 + tid;
        int h = e2 * 2;
        int c = h >> 6, i = h & 63;
        __half2 v = __halves2half2(Ysm[c * 64 + i], Ysm[c * 64 + i + 1]);
        int b = c >> 4, cl = c & 15;
        *(__half2*)&Yt[((size_t)(b * Dq + d)) * Lq + cl * 64 + i] = v;
    }
}

// ==================== GLU-fused HMMA GEMM (A from (B,D,L) layout) ============
__device__ __forceinline__ void glu_load_stage(uint32_t base, const __half* aYb,
                                               int d0, const __half* wa,
                                               const __half* wg, int K, int tid) {
#pragma unroll
    for (int i = 0; i < 4; ++i) {
        int idx = i * 256 + tid;
        int row = idx >> 4, c = idx & 15;
        uint32_t off = (uint32_t)(row * 256 + ((c * 16) ^ ((row & 7) << 4)));
        cp_async16(base + off, aYb + (size_t)(d0 + row) * Lq + c * 8);
    }
    const uint32_t stA = BM * BK * 2;   // 16KB
#pragma unroll
    for (int i = 0; i < 2; ++i) {
        int idx = i * 256 + tid;
        int row = idx >> 3, c = idx & 7;
        uint32_t off = (uint32_t)(row * 128 + ((c * 16) ^ ((row & 7) << 4)));
        cp_async16_ca(base + stA + off, wa + (size_t)row * K + c * 8);
    }
    const uint32_t stB = 64 * BK * 2;   // 8KB
#pragma unroll
    for (int i = 0; i < 2; ++i) {
        int idx = i * 256 + tid;
        int row = idx >> 3, c = idx & 7;
        uint32_t off = (uint32_t)(row * 128 + ((c * 16) ^ ((row & 7) << 4)));
        cp_async16_ca(base + stA + stB + off, wg + (size_t)row * K + c * 8);
    }
}

__global__ void __launch_bounds__(256)
hglu_kernel(const __half* __restrict__ Yt, const __half* __restrict__ W,
            const float* __restrict__ bias, __half* __restrict__ YG, int K) {
    extern __shared__ __align__(1024) char smem[];
    const uint32_t sb = smem_u32(smem);
    const int tid = threadIdx.x;
    const int lane = tid & 31;
    const int wid = tid >> 5;
    const int wm = (wid & 3) * 32;
    const int wn = (wid >> 2) * 32;
    const int bx = blockIdx.x, by = blockIdx.y;

    const uint32_t stA = BM * BK * 2;
    const uint32_t stB = 64 * BK * 2;
    const uint32_t stage_sz = stA + 2 * stB;
    const int nk = K / BK;

    const int bb = (by * BM) / Lq;
    const int l0 = (by * BM) % Lq;
    const __half* aYb = Yt + ((size_t)bb * Dq) * Lq + l0;
    const __half* Wa = W + (size_t)(bx * 64) * K;
    const __half* Wg = W + (size_t)(Dq + bx * 64) * K;

    glu_load_stage(sb + 0 * stage_sz, aYb, 0,  Wa,      Wg,      K, tid);
    cp_commit();
    glu_load_stage(sb + 1 * stage_sz, aYb, BK, Wa + BK, Wg + BK, K, tid);
    cp_commit();

    float acc[2][2][4][4];
#pragma unroll
    for (int i = 0; i < 2; ++i)
#pragma unroll
        for (int h = 0; h < 2; ++h)
#pragma unroll
            for (int j = 0; j < 4; ++j)
#pragma unroll
                for (int l = 0; l < 4; ++l) acc[i][h][j][l] = 0.0f;

    const int at_kr = (lane & 7) + ((lane >> 4) << 3);
    const int at_mc = ((lane >> 3) & 1) << 4;
    const int b_r  = ((lane >> 4) * 8) + (lane & 7);
    const int b_kb = ((lane >> 3) & 1) * 16;

    for (int kt = 0; kt < nk; ++kt) {
        cp_wait<STAGES - 2>();
        __syncthreads();

        if (kt + 2 < nk) {
            glu_load_stage(sb + ((kt + 2) % STAGES) * stage_sz,
                           aYb, (kt + 2) * BK, Wa + (kt + 2) * BK,
                           Wg + (kt + 2) * BK, K, tid);
        }
        cp_commit();

        const uint32_t baseA = sb + (kt % STAGES) * stage_sz;
        const uint32_t baseB = baseA + stA;

#pragma unroll
        for (int ks = 0; ks < 4; ++ks) {
            const int kb0 = ks * 32;
            uint32_t a_frag[2][4];
#pragma unroll
            for (int mt = 0; mt < 2; ++mt) {
                int krow = ks * 16 + at_kr;
                int colb = (wm + mt * 16) * 2 + at_mc;
                uint32_t addr = baseA + krow * 256 + (colb ^ ((krow & 7) << 4));
                ldsm_x4_trans(a_frag[mt], addr);
            }
            uint32_t b_frag[2][2][4];
#pragma unroll
            for (int h = 0; h < 2; ++h)
#pragma unroll
                for (int nb4 = 0; nb4 < 2; ++nb4) {
                    int row = wn + nb4 * 16 + b_r;
                    uint32_t addr = baseB + h * stB + row * 128
                                  + ((kb0 + b_kb) ^ ((row & 7) << 4));
                    ldsm_x4(b_frag[h][nb4], addr);
                }
#pragma unroll
            for (int mt = 0; mt < 2; ++mt)
#pragma unroll
                for (int h = 0; h < 2; ++h)
#pragma unroll
                    for (int nb = 0; nb < 4; ++nb) {
                        uint32_t b0 = b_frag[h][nb >> 1][(nb & 1) * 2 + 0];
                        uint32_t b1 = b_frag[h][nb >> 1][(nb & 1) * 2 + 1];
                        mma16816(acc[mt][h][nb], a_frag[mt], b0, b1);
                    }
        }
    }

    const int gr = lane >> 2;
    const int gc = (lane & 3) * 2;
#pragma unroll
    for (int mt = 0; mt < 2; ++mt) {
#pragma unroll
        for (int nb = 0; nb < 4; ++nb) {
            int row0 = by * BM + wm + mt * 16 + gr;
            int col  = bx * 64 + wn + nb * 8 + gc;
            float2 ba = *(const float2*)&bias[col];
            float2 bg = *(const float2*)&bias[Dq + col];
#pragma unroll
            for (int rr = 0; rr < 2; ++rr) {
                int row = row0 + rr * 8;
                float av0 = acc[mt][0][nb][rr * 2 + 0] + ba.x;
                float av1 = acc[mt][0][nb][rr * 2 + 1] + ba.y;
                float gv0 = acc[mt][1][nb][rr * 2 + 0] + bg.x;
                float gv1 = acc[mt][1][nb][rr * 2 + 1] + bg.y;
                float o0 = av0 / (1.0f + __expf(-gv0));
                float o1 = av1 / (1.0f + __expf(-gv1));
                *(__half2*)&YG[(size_t)row * Dq + col] = __floats2half2_rn(o0, o1);
            }
        }
    }
}

// ---------------- launch --------------------------------------------------
extern "C" void kernel_launch(void* const* d_in, const int* in_sizes, int n_in,
                              void* d_out, int out_size) {
    const float* x          = (const float*)d_in[0];
    const float* in_W       = (const float*)d_in[1];
    const float* in_b       = (const float*)d_in[2];
    const float* log_dt     = (const float*)d_in[3];
    const float* Cc         = (const float*)d_in[4];
    const float* log_A_real = (const float*)d_in[5];
    const float* A_imag     = (const float*)d_in[6];
    const float* D_skip     = (const float*)d_in[7];
    const float* glu_W      = (const float*)d_in[8];
    const float* glu_b      = (const float*)d_in[9];
    const float* out_W      = (const float*)d_in[10];
    const float* out_b      = (const float*)d_in[11];
    float* out = (float*)d_out;

    __half *xh, *ut, *yt, *ygh, *wih, *wgh, *woh;
    cudaGetSymbolAddress((void**)&xh,  g_xh);
    cudaGetSymbolAddress((void**)&ut,  g_ut);
    cudaGetSymbolAddress((void**)&yt,  g_yt);
    cudaGetSymbolAddress((void**)&ygh, g_ygh);
    cudaGetSymbolAddress((void**)&wih, g_wih);
    cudaGetSymbolAddress((void**)&wgh, g_wgh);
    cudaGetSymbolAddress((void**)&woh, g_woh);

    const int SMEM_SZ = STAGES * 2 * BM * BK * 2;   // 96KB
    cudaFuncSetAttribute(hgemm_kernel<1>, cudaFuncAttributeMaxDynamicSharedMemorySize, SMEM_SZ);
    cudaFuncSetAttribute(hgemm_kernel<4>, cudaFuncAttributeMaxDynamicSharedMemorySize, SMEM_SZ);
    cudaFuncSetAttribute(hglu_kernel, cudaFuncAttributeMaxDynamicSharedMemorySize, SMEM_SZ);
    cudaFuncSetAttribute(s4chunk_kernel, cudaFuncAttributeMaxDynamicSharedMemorySize, SM_TOTAL_S4);

    // 1) fp16 conversions
    {
        int total4 = N4X + N4I + N4G + N4O;
        cvt_all_kernel<<<(total4 + 255) / 256, 256>>>(x, in_W, glu_W, out_W,
                                                      xh, wih, wgh, woh);
    }

    // 2) in_proj computed transposed: ut[d][m] = in_W @ x^T, written as (B, D, L)
    {
        dim3 grid(Mq / BN, Dq / BM);
        hgemm_kernel<4><<<grid, 256, SMEM_SZ>>>(wih, xh, in_b, nullptr, ut, Dq, Mq, Dq);
    }

    // 3) chunked SSM (prep fused) + skip + GELU -> Yt (B, D, L)
    s4chunk_kernel<<<Dq, 256, SM_TOTAL_S4>>>(ut, log_dt, Cc, log_A_real, A_imag,
                                             D_skip, yt);

    // 4) GLU GEMM (A read transposed from yt) fused with a*sigmoid(g) -> fp16
    {
        dim3 grid(Dq / 64, Mq / BM);
        hglu_kernel<<<grid, 256, SMEM_SZ>>>(yt, wgh, glu_b, ygh, Dq);
    }

    // 5) out_proj + fp16 residual
    {
        dim3 grid(Dq / BN, Mq / BM);
        hgemm_kernel<1><<<grid, 256, SMEM_SZ>>>(ygh, woh, out_b, xh, out, Mq, Dq, Dq);
    }
}

// round 15
// speedup vs baseline: 1.0404x; 1.0404x over previous
#include <cuda_runtime.h>
#include <cuda_fp16.h>
#include <math.h>
#include <cstdint>

// Problem constants
#define Bq   8
#define Lq   1024
#define Dq   1024
#define Nq   32
#define Mq   (Bq * Lq)          // 8192 rows

#define BM 128
#define BN 128
#define BK 64
#define STAGES 3

// ---------------- scratch (device globals; no allocations allowed) ----------
__device__ __align__(128) __half g_xh [(size_t)Mq * Dq];       // x fp16
__device__ __align__(128) __half g_ut [(size_t)Mq * Dq];       // in_proj out (B, D, L)
__device__ __align__(128) __half g_yt [(size_t)Mq * Dq];       // SSM out (B, D, L)
__device__ __align__(128) __half g_ygh[(size_t)Mq * Dq];       // GLU out fp16
__device__ __align__(128) __half g_wih[(size_t)Dq * Dq];       // in_W fp16
__device__ __align__(128) __half g_wgh[(size_t)2 * Dq * Dq];   // glu_W fp16
__device__ __align__(128) __half g_woh[(size_t)Dq * Dq];       // out_W fp16

// ==================== PTX helpers (baseline sm_80+ features only) ===========
__device__ __forceinline__ uint32_t smem_u32(const void* p) {
    return (uint32_t)__cvta_generic_to_shared(p);
}
__device__ __forceinline__ void cp_async16(uint32_t dst, const void* src) {
    asm volatile("cp.async.cg.shared.global [%0], [%1], 16;" :: "r"(dst), "l"(src));
}
__device__ __forceinline__ void cp_commit() {
    asm volatile("cp.async.commit_group;" ::: "memory");
}
template <int N>
__device__ __forceinline__ void cp_wait() {
    asm volatile("cp.async.wait_group %0;" :: "n"(N) : "memory");
}
__device__ __forceinline__ void ldsm_x4(uint32_t* r, uint32_t addr) {
    asm volatile("ldmatrix.sync.aligned.m8n8.x4.shared.b16 {%0,%1,%2,%3}, [%4];"
                 : "=r"(r[0]), "=r"(r[1]), "=r"(r[2]), "=r"(r[3]) : "r"(addr));
}
__device__ __forceinline__ void ldsm_x4_trans(uint32_t* r, uint32_t addr) {
    asm volatile("ldmatrix.sync.aligned.m8n8.x4.trans.shared.b16 {%0,%1,%2,%3}, [%4];"
                 : "=r"(r[0]), "=r"(r[1]), "=r"(r[2]), "=r"(r[3]) : "r"(addr));
}
__device__ __forceinline__ void mma16816(float* c, const uint32_t* a, uint32_t b0, uint32_t b1) {
    asm volatile("mma.sync.aligned.m16n8k16.row.col.f32.f16.f16.f32 "
                 "{%0,%1,%2,%3}, {%4,%5,%6,%7}, {%8,%9}, {%0,%1,%2,%3};"
                 : "+f"(c[0]), "+f"(c[1]), "+f"(c[2]), "+f"(c[3])
                 : "r"(a[0]), "r"(a[1]), "r"(a[2]), "r"(a[3]), "r"(b0), "r"(b1));
}

// ---------------- fp32 -> fp16 conversion (all tensors in one launch) -------
#define N4X (Mq * Dq / 4)
#define N4I (Dq * Dq / 4)
#define N4G (2 * Dq * Dq / 4)
#define N4O (Dq * Dq / 4)
__global__ void cvt_all_kernel(const float* __restrict__ x,
                               const float* __restrict__ wi,
                               const float* __restrict__ wg,
                               const float* __restrict__ wo,
                               __half* __restrict__ xh, __half* __restrict__ wih,
                               __half* __restrict__ wgh, __half* __restrict__ woh) {
    int i = blockIdx.x * blockDim.x + threadIdx.x;
    const float* src;
    __half* dst;
    int j = i;
    if (j < N4X) { src = x; dst = xh; }
    else if ((j -= N4X) < N4I) { src = wi; dst = wih; }
    else if ((j -= N4I) < N4G) { src = wg; dst = wgh; }
    else if ((j -= N4G) < N4O) { src = wo; dst = woh; }
    else return;
    float4 v = ((const float4*)src)[j];
    __half2 h0 = __floats2half2_rn(v.x, v.y);
    __half2 h1 = __floats2half2_rn(v.z, v.w);
    uint2 o;
    o.x = *(uint32_t*)&h0;
    o.y = *(uint32_t*)&h1;
    ((uint2*)dst)[j] = o;
}

// ==================== HMMA fp16 GEMM (main projections) =====================
__device__ __forceinline__ void gemm_load_stage(uint32_t base, const __half* as,
                                                const __half* ws, int K, int tid) {
#pragma unroll
    for (int i = 0; i < 4; ++i) {
        int idx = i * 256 + tid;
        int row = idx >> 3, c = idx & 7;
        uint32_t off = (uint32_t)(row * 128 + ((c * 16) ^ ((row & 7) << 4)));
        cp_async16(base + off, as + (size_t)row * K + c * 8);
    }
    const uint32_t stA = BM * BK * 2;
#pragma unroll
    for (int i = 0; i < 4; ++i) {
        int idx = i * 256 + tid;
        int row = idx >> 3, c = idx & 7;
        uint32_t off = (uint32_t)(row * 128 + ((c * 16) ^ ((row & 7) << 4)));
        cp_async16(base + stA + off, ws + (size_t)row * K + c * 8);
    }
}

// EPI: 1 = fp32 out + bias(col) + fp16 residual, row-major C (M x Nn)
//      4 = fp16 out + bias(row),  C written as (B, D, L): row = d, col = m
template <int EPI>
__global__ void __launch_bounds__(256)
hgemm_kernel(const __half* __restrict__ A, const __half* __restrict__ W,
             const float* __restrict__ bias, const __half* __restrict__ Rh,
             void* __restrict__ Cv, int M, int Nn, int K) {
    extern __shared__ __align__(1024) char smem[];
    const uint32_t sb = smem_u32(smem);
    const int tid = threadIdx.x;
    const int lane = tid & 31;
    const int wid = tid >> 5;
    const int wm = (wid & 3) * 32;
    const int wn = (wid >> 2) * 64;
    const int bx = blockIdx.x, by = blockIdx.y;

    const uint32_t stA = BM * BK * 2;
    const uint32_t stage_sz = 2 * stA;
    const int nk = K / BK;

    const __half* Ab = A + (size_t)(by * BM) * K;
    const __half* Wb = W + (size_t)(bx * BN) * K;

    gemm_load_stage(sb + 0 * stage_sz, Ab, Wb, K, tid);
    cp_commit();
    gemm_load_stage(sb + 1 * stage_sz, Ab + BK, Wb + BK, K, tid);
    cp_commit();

    float acc[2][8][4];
#pragma unroll
    for (int i = 0; i < 2; ++i)
#pragma unroll
        for (int j = 0; j < 8; ++j)
#pragma unroll
            for (int l = 0; l < 4; ++l) acc[i][j][l] = 0.0f;

    const int a_r  = lane & 15;
    const int a_kb = (lane >> 4) * 16;
    const int b_r  = ((lane >> 4) * 8) + (lane & 7);
    const int b_kb = ((lane >> 3) & 1) * 16;

    for (int kt = 0; kt < nk; ++kt) {
        cp_wait<STAGES - 2>();
        __syncthreads();

        if (kt + 2 < nk) {
            gemm_load_stage(sb + ((kt + 2) % STAGES) * stage_sz,
                            Ab + (kt + 2) * BK, Wb + (kt + 2) * BK, K, tid);
        }
        cp_commit();

        const uint32_t baseA = sb + (kt % STAGES) * stage_sz;
        const uint32_t baseB = baseA + stA;

#pragma unroll
        for (int ks = 0; ks < 4; ++ks) {
            const int kb0 = ks * 32;
            uint32_t a_frag[2][4];
#pragma unroll
            for (int mt = 0; mt < 2; ++mt) {
                int row = wm + mt * 16 + a_r;
                uint32_t addr = baseA + row * 128 + ((kb0 + a_kb) ^ ((row & 7) << 4));
                ldsm_x4(a_frag[mt], addr);
            }
            uint32_t b_frag[4][4];
#pragma unroll
            for (int nb4 = 0; nb4 < 4; ++nb4) {
                int row = wn + nb4 * 16 + b_r;
                uint32_t addr = baseB + row * 128 + ((kb0 + b_kb) ^ ((row & 7) << 4));
                ldsm_x4(b_frag[nb4], addr);
            }
#pragma unroll
            for (int mt = 0; mt < 2; ++mt)
#pragma unroll
                for (int nb = 0; nb < 8; ++nb) {
                    uint32_t b0 = b_frag[nb >> 1][(nb & 1) * 2 + 0];
                    uint32_t b1 = b_frag[nb >> 1][(nb & 1) * 2 + 1];
                    mma16816(acc[mt][nb], a_frag[mt], b0, b1);
                }
        }
    }

    const int gr = lane >> 2;
    const int gc = (lane & 3) * 2;

    if (EPI == 1) {
        float* C = (float*)Cv;
#pragma unroll
        for (int mt = 0; mt < 2; ++mt) {
#pragma unroll
            for (int nb = 0; nb < 8; ++nb) {
                int row0 = by * BM + wm + mt * 16 + gr;
                int col  = bx * BN + wn + nb * 8 + gc;
                float2 bs = *(const float2*)&bias[col];
                float2 v0, v1;
                v0.x = acc[mt][nb][0] + bs.x;
                v0.y = acc[mt][nb][1] + bs.y;
                v1.x = acc[mt][nb][2] + bs.x;
                v1.y = acc[mt][nb][3] + bs.y;
                __half2 r0 = *(const __half2*)&Rh[(size_t)row0 * Nn + col];
                __half2 r1 = *(const __half2*)&Rh[(size_t)(row0 + 8) * Nn + col];
                v0.x += __low2float(r0); v0.y += __high2float(r0);
                v1.x += __low2float(r1); v1.y += __high2float(r1);
                *(float2*)&C[(size_t)row0 * Nn + col] = v0;
                *(float2*)&C[(size_t)(row0 + 8) * Nn + col] = v1;
            }
        }
    } else {
        // EPI == 4: rows = channels d, cols = m (one batch per tile).
        __half* C = (__half*)Cv;
        const int b  = (bx * BN) / Lq;
        const int l0 = (bx * BN) % Lq;
#pragma unroll
        for (int mt = 0; mt < 2; ++mt) {
            int d0 = by * BM + wm + mt * 16 + gr;
            float bs0 = bias[d0];
            float bs1 = bias[d0 + 8];
            __half* r0p = C + ((size_t)(b * Dq + d0)) * Lq + l0;
            __half* r1p = C + ((size_t)(b * Dq + d0 + 8)) * Lq + l0;
#pragma unroll
            for (int nb = 0; nb < 8; ++nb) {
                int cl = wn + nb * 8 + gc;
                *(__half2*)&r0p[cl] = __floats2half2_rn(acc[mt][nb][0] + bs0,
                                                        acc[mt][nb][1] + bs0);
                *(__half2*)&r1p[cl] = __floats2half2_rn(acc[mt][nb][2] + bs1,
                                                        acc[mt][nb][3] + bs1);
            }
        }
    }
}

// ==================== chunked SSM kernel (prep fused in) =====================
#define SM_KT  0
#define SM_P   8192
#define SM_SO  16384
#define SM_U   24576
#define SM_SH  40960
#define SM_AGG 57344
#define SM_WT  74240
#define SM_KS  74496
#define AGG_STRIDE 132
#define SM_TOTAL_S4 74752

__device__ __forceinline__ void small_gemm(uint32_t Abase, uint32_t Bbase,
                                           float acc[8][4], int wmi, int wn, int lane) {
    const int a_r  = lane & 15;
    const int a_kb = (lane >> 4) * 16;
    const int b_r  = ((lane >> 4) * 8) + (lane & 7);
    const int b_kb = ((lane >> 3) & 1) * 16;
#pragma unroll
    for (int ks = 0; ks < 4; ++ks) {
        const int kb0 = ks * 32;
        uint32_t a_frag[4];
        {
            int row = wmi + a_r;
            ldsm_x4(a_frag, Abase + row * 128 + ((kb0 + a_kb) ^ ((row & 7) << 4)));
        }
        uint32_t b_frag[4][4];
#pragma unroll
        for (int nb4 = 0; nb4 < 4; ++nb4) {
            int row = wn + nb4 * 16 + b_r;
            ldsm_x4(b_frag[nb4], Bbase + row * 128 + ((kb0 + b_kb) ^ ((row & 7) << 4)));
        }
#pragma unroll
        for (int nb = 0; nb < 8; ++nb)
            mma16816(acc[nb], a_frag,
                     b_frag[nb >> 1][(nb & 1) * 2 + 0],
                     b_frag[nb >> 1][(nb & 1) * 2 + 1]);
    }
}

// half store at swizzled (row, col) in a 128B-row tile
__device__ __forceinline__ void st_sw(char* smem, uint32_t base, int row, int col, float v) {
    *(__half*)(smem + base + row * 128 + ((col * 2) ^ ((row & 7) << 4))) = __float2half(v);
}

__global__ void __launch_bounds__(256, 3)
s4chunk_kernel(const __half* __restrict__ Ut,
               const float* __restrict__ log_dt, const float* __restrict__ Cc,
               const float* __restrict__ log_A_real, const float* __restrict__ A_imag,
               const float* __restrict__ dskip, __half* __restrict__ Yt) {
    extern __shared__ __align__(1024) char smem[];
    const uint32_t sb = smem_u32(smem);
    const int d = blockIdx.x;
    const int tid = threadIdx.x;
    const int lane = tid & 31;
    const int wid = tid >> 5;
    const int wmi = (wid & 3) * 16;
    const int wn  = (wid >> 2) * 64;

    __half* AGG16 = (__half*)(smem + SM_AGG);   // [64][132] fp16
    __half* Ysm   = (__half*)(smem + SM_AGG);   // reused: [128][64] fp16
    float*  WT    = (float*)(smem + SM_WT);     // [32][2]
    float*  KS    = (float*)(smem + SM_KS);     // [64]

    // ---- kick off U tile load first (overlaps prep math) ----
#pragma unroll
    for (int i = 0; i < 4; ++i) {
        int e = i * 256 + tid;
        int row = e >> 3, c8 = e & 7;
        int b = row >> 4, cl = row & 15;
        uint32_t off = row * 128 + ((c8 * 16) ^ ((row & 7) << 4));
        cp_async16(sb + SM_U + off,
                   Ut + ((size_t)(b * Dq + d)) * Lq + cl * 64 + c8 * 8);
    }
    cp_commit();

    // ---- fused prep: each warp computes 8 powers (p0 = wid*8) ----
    {
        const int n = lane;
        const int idx = d * Nq + n;
        float dt   = expf(log_dt[d]);
        float a_re = -expf(log_A_real[idx]);
        float a_im = A_imag[idx];
        float ex   = expf(a_re * dt);
        float wre  = ex * cosf(a_im * dt);
        float wim  = ex * sinf(a_im * dt);
        float n_re = wre - 1.0f, n_im = wim;
        float den  = a_re * a_re + a_im * a_im;
        float f_re = (n_re * a_re + n_im * a_im) / den;
        float f_im = (n_im * a_re - n_re * a_im) / den;
        float C_re = Cc[idx * 2 + 0];
        float C_im = Cc[idx * 2 + 1];
        float cre  = 2.0f * (C_re * f_re - C_im * f_im);
        float cim  = 2.0f * (C_re * f_im + C_im * f_re);

        // w^(p0) via binary exponentiation
        int e = wid * 8;
        float pr = 1.0f, pi = 0.0f, br = wre, bi = wim;
        while (e) {
            if (e & 1) {
                float t = pr * br - pi * bi;
                pi = pr * bi + pi * br;
                pr = t;
            }
            float t2 = br * br - bi * bi;
            bi = 2.0f * br * bi;
            br = t2;
            e >>= 1;
        }
        float qr = cre * pr - cim * pi;
        float qi = cre * pi + cim * pr;

#pragma unroll
        for (int j = 0; j < 8; ++j) {
            int p = wid * 8 + j;
            st_sw(smem, SM_P, n, 63 - p, pr);
            st_sw(smem, SM_P, 32 + n, 63 - p, pi);
            float s = qr;
#pragma unroll
            for (int off = 16; off; off >>= 1)
                s += __shfl_xor_sync(0xffffffffu, s, off);
            if (n == 0) KS[p] = s;
            if (p >= 1) {
                st_sw(smem, SM_SO, p - 1, n, qr);
                st_sw(smem, SM_SO, p - 1, 32 + n, -qi);
            }
            float npr = pr * wre - pi * wim;
            float npi = pr * wim + pi * wre;
            pr = npr; pi = npi;
            float nqr = qr * wre - qi * wim;
            float nqi = qr * wim + qi * wre;
            qr = nqr; qi = nqi;
        }
        if (wid == 7) {
            st_sw(smem, SM_SO, 63, n, qr);
            st_sw(smem, SM_SO, 63, 32 + n, -qi);
            WT[n * 2 + 0] = pr;
            WT[n * 2 + 1] = pi;
        }
    }
    __syncthreads();

    // ---- KT fill: KT[i][j] = k[i-j] (j<=i) + skip on diagonal ----
    {
        const float skip = dskip[d];
        for (int ee = tid; ee < 4096; ee += 256) {
            int i = ee >> 6, j = ee & 63;
            float v = (j <= i ? KS[i - j] : 0.0f) + (i == j ? skip : 0.0f);
            st_sw(smem, SM_KT, i, j, v);
        }
    }
    cp_wait<0>();
    __syncthreads();

    const int gr = lane >> 2;
    const int gc = (lane & 3) * 2;

    // GEMM1: AGG = P @ U^T  (fp16 staging, padded stride)
    {
        float agg[8][4];
#pragma unroll
        for (int j = 0; j < 8; ++j)
#pragma unroll
            for (int l = 0; l < 4; ++l) agg[j][l] = 0.0f;
        small_gemm(sb + SM_P, sb + SM_U, agg, wmi, wn, lane);
#pragma unroll
        for (int nb = 0; nb < 8; ++nb) {
            int col = wn + nb * 8 + gc;
            *(__half2*)&AGG16[(wmi + gr) * AGG_STRIDE + col] =
                __floats2half2_rn(agg[nb][0], agg[nb][1]);
            *(__half2*)&AGG16[(wmi + gr + 8) * AGG_STRIDE + col] =
                __floats2half2_rn(agg[nb][2], agg[nb][3]);
        }
    }
    __syncthreads();

    // boundary-state recurrence (fp32 state, fp16 AGG reads)
    {
        int n = tid & 31, b = tid >> 5;
        float wtr = WT[n * 2 + 0];
        float wti = WT[n * 2 + 1];
        float Er = 0.0f, Ei = 0.0f;
        for (int cl = 0; cl < 16; ++cl) {
            int c = b * 16 + cl;
            *(__half*)(smem + SM_SH + c * 128 + ((n * 2) ^ ((c & 7) << 4))) = __float2half(Er);
            *(__half*)(smem + SM_SH + c * 128 + (((32 + n) * 2) ^ ((c & 7) << 4))) = __float2half(Ei);
            float ar = __half2float(AGG16[n * AGG_STRIDE + c]);
            float ai = __half2float(AGG16[(32 + n) * AGG_STRIDE + c]);
            float nEr = fmaf(wtr, Er, fmaf(-wti, Ei, ar));
            float nEi = fmaf(wtr, Ei, fmaf(wti, Er, ai));
            Er = nEr; Ei = nEi;
        }
    }
    __syncthreads();

    // GEMM2 + GEMM3: Y = KT @ U^T + SO @ S_h
    float acc[8][4];
#pragma unroll
    for (int j = 0; j < 8; ++j)
#pragma unroll
        for (int l = 0; l < 4; ++l) acc[j][l] = 0.0f;
    small_gemm(sb + SM_KT, sb + SM_U,  acc, wmi, wn, lane);
    small_gemm(sb + SM_SO, sb + SM_SH, acc, wmi, wn, lane);

    // GELU directly on accumulator, stage to Ysm
#pragma unroll
    for (int nb = 0; nb < 8; ++nb) {
#pragma unroll
        for (int q = 0; q < 4; ++q) {
            int i = wmi + gr + (q >> 1) * 8;
            int c = wn + nb * 8 + gc + (q & 1);
            float v = acc[nb][q];
            float g = 0.5f * v * (1.0f + erff(v * 0.70710678118654752f));
            Ysm[c * 64 + i] = __float2half(g);
        }
    }
    __syncthreads();

#pragma unroll
    for (int it = 0; it < 16; ++it) {
        int e2 = it * 256 + tid;
        int h = e2 * 2;
        int c = h >> 6, i = h & 63;
        __half2 v = __halves2half2(Ysm[c * 64 + i], Ysm[c * 64 + i + 1]);
        int b = c >> 4, cl = c & 15;
        *(__half2*)&Yt[((size_t)(b * Dq + d)) * Lq + cl * 64 + i] = v;
    }
}

// ==================== GLU-fused HMMA GEMM (A from (B,D,L) layout) ============
__device__ __forceinline__ void glu_load_stage(uint32_t base, const __half* aYb,
                                               int d0, const __half* wa,
                                               const __half* wg, int K, int tid) {
#pragma unroll
    for (int i = 0; i < 4; ++i) {
        int idx = i * 256 + tid;
        int row = idx >> 4, c = idx & 15;
        uint32_t off = (uint32_t)(row * 256 + ((c * 16) ^ ((row & 7) << 4)));
        cp_async16(base + off, aYb + (size_t)(d0 + row) * Lq + c * 8);
    }
    const uint32_t stA = BM * BK * 2;   // 16KB
#pragma unroll
    for (int i = 0; i < 2; ++i) {
        int idx = i * 256 + tid;
        int row = idx >> 3, c = idx & 7;
        uint32_t off = (uint32_t)(row * 128 + ((c * 16) ^ ((row & 7) << 4)));
        cp_async16(base + stA + off, wa + (size_t)row * K + c * 8);
    }
    const uint32_t stB = 64 * BK * 2;   // 8KB
#pragma unroll
    for (int i = 0; i < 2; ++i) {
        int idx = i * 256 + tid;
        int row = idx >> 3, c = idx & 7;
        uint32_t off = (uint32_t)(row * 128 + ((c * 16) ^ ((row & 7) << 4)));
        cp_async16(base + stA + stB + off, wg + (size_t)row * K + c * 8);
    }
}

__global__ void __launch_bounds__(256)
hglu_kernel(const __half* __restrict__ Yt, const __half* __restrict__ W,
            const float* __restrict__ bias, __half* __restrict__ YG, int K) {
    extern __shared__ __align__(1024) char smem[];
    const uint32_t sb = smem_u32(smem);
    const int tid = threadIdx.x;
    const int lane = tid & 31;
    const int wid = tid >> 5;
    const int wm = (wid & 3) * 32;
    const int wn = (wid >> 2) * 32;
    const int bx = blockIdx.x, by = blockIdx.y;

    const uint32_t stA = BM * BK * 2;
    const uint32_t stB = 64 * BK * 2;
    const uint32_t stage_sz = stA + 2 * stB;
    const int nk = K / BK;

    const int bb = (by * BM) / Lq;
    const int l0 = (by * BM) % Lq;
    const __half* aYb = Yt + ((size_t)bb * Dq) * Lq + l0;
    const __half* Wa = W + (size_t)(bx * 64) * K;
    const __half* Wg = W + (size_t)(Dq + bx * 64) * K;

    glu_load_stage(sb + 0 * stage_sz, aYb, 0,  Wa,      Wg,      K, tid);
    cp_commit();
    glu_load_stage(sb + 1 * stage_sz, aYb, BK, Wa + BK, Wg + BK, K, tid);
    cp_commit();

    float acc[2][2][4][4];
#pragma unroll
    for (int i = 0; i < 2; ++i)
#pragma unroll
        for (int h = 0; h < 2; ++h)
#pragma unroll
            for (int j = 0; j < 4; ++j)
#pragma unroll
                for (int l = 0; l < 4; ++l) acc[i][h][j][l] = 0.0f;

    const int at_kr = (lane & 7) + ((lane >> 4) << 3);
    const int at_mc = ((lane >> 3) & 1) << 4;
    const int b_r  = ((lane >> 4) * 8) + (lane & 7);
    const int b_kb = ((lane >> 3) & 1) * 16;

    for (int kt = 0; kt < nk; ++kt) {
        cp_wait<STAGES - 2>();
        __syncthreads();

        if (kt + 2 < nk) {
            glu_load_stage(sb + ((kt + 2) % STAGES) * stage_sz,
                           aYb, (kt + 2) * BK, Wa + (kt + 2) * BK,
                           Wg + (kt + 2) * BK, K, tid);
        }
        cp_commit();

        const uint32_t baseA = sb + (kt % STAGES) * stage_sz;
        const uint32_t baseB = baseA + stA;

#pragma unroll
        for (int ks = 0; ks < 4; ++ks) {
            const int kb0 = ks * 32;
            uint32_t a_frag[2][4];
#pragma unroll
            for (int mt = 0; mt < 2; ++mt) {
                int krow = ks * 16 + at_kr;
                int colb = (wm + mt * 16) * 2 + at_mc;
                uint32_t addr = baseA + krow * 256 + (colb ^ ((krow & 7) << 4));
                ldsm_x4_trans(a_frag[mt], addr);
            }
            uint32_t b_frag[2][2][4];
#pragma unroll
            for (int h = 0; h < 2; ++h)
#pragma unroll
                for (int nb4 = 0; nb4 < 2; ++nb4) {
                    int row = wn + nb4 * 16 + b_r;
                    uint32_t addr = baseB + h * stB + row * 128
                                  + ((kb0 + b_kb) ^ ((row & 7) << 4));
                    ldsm_x4(b_frag[h][nb4], addr);
                }
#pragma unroll
            for (int mt = 0; mt < 2; ++mt)
#pragma unroll
                for (int h = 0; h < 2; ++h)
#pragma unroll
                    for (int nb = 0; nb < 4; ++nb) {
                        uint32_t b0 = b_frag[h][nb >> 1][(nb & 1) * 2 + 0];
                        uint32_t b1 = b_frag[h][nb >> 1][(nb & 1) * 2 + 1];
                        mma16816(acc[mt][h][nb], a_frag[mt], b0, b1);
                    }
        }
    }

    const int gr = lane >> 2;
    const int gc = (lane & 3) * 2;
#pragma unroll
    for (int mt = 0; mt < 2; ++mt) {
#pragma unroll
        for (int nb = 0; nb < 4; ++nb) {
            int row0 = by * BM + wm + mt * 16 + gr;
            int col  = bx * 64 + wn + nb * 8 + gc;
            float2 ba = *(const float2*)&bias[col];
            float2 bg = *(const float2*)&bias[Dq + col];
#pragma unroll
            for (int rr = 0; rr < 2; ++rr) {
                int row = row0 + rr * 8;
                float av0 = acc[mt][0][nb][rr * 2 + 0] + ba.x;
                float av1 = acc[mt][0][nb][rr * 2 + 1] + ba.y;
                float gv0 = acc[mt][1][nb][rr * 2 + 0] + bg.x;
                float gv1 = acc[mt][1][nb][rr * 2 + 1] + bg.y;
                float o0 = av0 / (1.0f + __expf(-gv0));
                float o1 = av1 / (1.0f + __expf(-gv1));
                *(__half2*)&YG[(size_t)row * Dq + col] = __floats2half2_rn(o0, o1);
            }
        }
    }
}

// ---------------- launch --------------------------------------------------
extern "C" void kernel_launch(void* const* d_in, const int* in_sizes, int n_in,
                              void* d_out, int out_size) {
    const float* x          = (const float*)d_in[0];
    const float* in_W       = (const float*)d_in[1];
    const float* in_b       = (const float*)d_in[2];
    const float* log_dt     = (const float*)d_in[3];
    const float* Cc         = (const float*)d_in[4];
    const float* log_A_real = (const float*)d_in[5];
    const float* A_imag     = (const float*)d_in[6];
    const float* D_skip     = (const float*)d_in[7];
    const float* glu_W      = (const float*)d_in[8];
    const float* glu_b      = (const float*)d_in[9];
    const float* out_W      = (const float*)d_in[10];
    const float* out_b      = (const float*)d_in[11];
    float* out = (float*)d_out;

    __half *xh, *ut, *yt, *ygh, *wih, *wgh, *woh;
    cudaGetSymbolAddress((void**)&xh,  g_xh);
    cudaGetSymbolAddress((void**)&ut,  g_ut);
    cudaGetSymbolAddress((void**)&yt,  g_yt);
    cudaGetSymbolAddress((void**)&ygh, g_ygh);
    cudaGetSymbolAddress((void**)&wih, g_wih);
    cudaGetSymbolAddress((void**)&wgh, g_wgh);
    cudaGetSymbolAddress((void**)&woh, g_woh);

    const int SMEM_SZ = STAGES * 2 * BM * BK * 2;   // 96KB
    cudaFuncSetAttribute(hgemm_kernel<1>, cudaFuncAttributeMaxDynamicSharedMemorySize, SMEM_SZ);
    cudaFuncSetAttribute(hgemm_kernel<4>, cudaFuncAttributeMaxDynamicSharedMemorySize, SMEM_SZ);
    cudaFuncSetAttribute(hglu_kernel, cudaFuncAttributeMaxDynamicSharedMemorySize, SMEM_SZ);
    cudaFuncSetAttribute(s4chunk_kernel, cudaFuncAttributeMaxDynamicSharedMemorySize, SM_TOTAL_S4);

    // 1) fp16 conversions
    {
        int total4 = N4X + N4I + N4G + N4O;
        cvt_all_kernel<<<(total4 + 255) / 256, 256>>>(x, in_W, glu_W, out_W,
                                                      xh, wih, wgh, woh);
    }

    // 2) in_proj computed transposed: ut[d][m] = in_W @ x^T, written as (B, D, L)
    {
        dim3 grid(Mq / BN, Dq / BM);
        hgemm_kernel<4><<<grid, 256, SMEM_SZ>>>(wih, xh, in_b, nullptr, ut, Dq, Mq, Dq);
    }

    // 3) chunked SSM (prep fused) + skip + GELU -> Yt (B, D, L)
    s4chunk_kernel<<<Dq, 256, SM_TOTAL_S4>>>(ut, log_dt, Cc, log_A_real, A_imag,
                                             D_skip, yt);

    // 4) GLU GEMM (A read transposed from yt) fused with a*sigmoid(g) -> fp16
    {
        dim3 grid(Dq / 64, Mq / BM);
        hglu_kernel<<<grid, 256, SMEM_SZ>>>(yt, wgh, glu_b, ygh, Dq);
    }

    // 5) out_proj + fp16 residual
    {
        dim3 grid(Dq / BN, Mq / BM);
        hgemm_kernel<1><<<grid, 256, SMEM_SZ>>>(ygh, woh, out_b, xh, out, Mq, Dq, Dq);
    }
}

// round 16
// speedup vs baseline: 1.0488x; 1.0081x over previous
#include <cuda_runtime.h>
#include <cuda_fp16.h>
#include <math.h>
#include <cstdint>

// Problem constants
#define Bq   8
#define Lq   1024
#define Dq   1024
#define Nq   32
#define Mq   (Bq * Lq)          // 8192 rows

#define BM 128
#define BN 128
#define BK 64
#define STAGES 3

// ---------------- scratch (device globals; no allocations allowed) ----------
__device__ __align__(128) __half g_xh [(size_t)Mq * Dq];       // x fp16
__device__ __align__(128) __half g_ut [(size_t)Mq * Dq];       // in_proj out (B, D, L)
__device__ __align__(128) __half g_yt [(size_t)Mq * Dq];       // SSM out (B, D, L)
__device__ __align__(128) __half g_ygh[(size_t)Mq * Dq];       // GLU out fp16
__device__ __align__(128) __half g_wih[(size_t)Dq * Dq];       // in_W fp16
__device__ __align__(128) __half g_wgh[(size_t)2 * Dq * Dq];   // glu_W fp16
__device__ __align__(128) __half g_woh[(size_t)Dq * Dq];       // out_W fp16

// ==================== PTX helpers (baseline sm_80+ features only) ===========
__device__ __forceinline__ uint32_t smem_u32(const void* p) {
    return (uint32_t)__cvta_generic_to_shared(p);
}
__device__ __forceinline__ void cp_async16(uint32_t dst, const void* src) {
    asm volatile("cp.async.cg.shared.global [%0], [%1], 16;" :: "r"(dst), "l"(src));
}
__device__ __forceinline__ void cp_commit() {
    asm volatile("cp.async.commit_group;" ::: "memory");
}
template <int N>
__device__ __forceinline__ void cp_wait() {
    asm volatile("cp.async.wait_group %0;" :: "n"(N) : "memory");
}
__device__ __forceinline__ void ldsm_x4(uint32_t* r, uint32_t addr) {
    asm volatile("ldmatrix.sync.aligned.m8n8.x4.shared.b16 {%0,%1,%2,%3}, [%4];"
                 : "=r"(r[0]), "=r"(r[1]), "=r"(r[2]), "=r"(r[3]) : "r"(addr));
}
__device__ __forceinline__ void ldsm_x4_trans(uint32_t* r, uint32_t addr) {
    asm volatile("ldmatrix.sync.aligned.m8n8.x4.trans.shared.b16 {%0,%1,%2,%3}, [%4];"
                 : "=r"(r[0]), "=r"(r[1]), "=r"(r[2]), "=r"(r[3]) : "r"(addr));
}
__device__ __forceinline__ void mma16816(float* c, const uint32_t* a, uint32_t b0, uint32_t b1) {
    asm volatile("mma.sync.aligned.m16n8k16.row.col.f32.f16.f16.f32 "
                 "{%0,%1,%2,%3}, {%4,%5,%6,%7}, {%8,%9}, {%0,%1,%2,%3};"
                 : "+f"(c[0]), "+f"(c[1]), "+f"(c[2]), "+f"(c[3])
                 : "r"(a[0]), "r"(a[1]), "r"(a[2]), "r"(a[3]), "r"(b0), "r"(b1));
}

// ---------------- fp32 -> fp16 conversion (all tensors in one launch) -------
#define N4X (Mq * Dq / 4)
#define N4I (Dq * Dq / 4)
#define N4G (2 * Dq * Dq / 4)
#define N4O (Dq * Dq / 4)
__global__ void cvt_all_kernel(const float* __restrict__ x,
                               const float* __restrict__ wi,
                               const float* __restrict__ wg,
                               const float* __restrict__ wo,
                               __half* __restrict__ xh, __half* __restrict__ wih,
                               __half* __restrict__ wgh, __half* __restrict__ woh) {
    int i = blockIdx.x * blockDim.x + threadIdx.x;
    const float* src;
    __half* dst;
    int j = i;
    if (j < N4X) { src = x; dst = xh; }
    else if ((j -= N4X) < N4I) { src = wi; dst = wih; }
    else if ((j -= N4I) < N4G) { src = wg; dst = wgh; }
    else if ((j -= N4G) < N4O) { src = wo; dst = woh; }
    else return;
    float4 v = ((const float4*)src)[j];
    __half2 h0 = __floats2half2_rn(v.x, v.y);
    __half2 h1 = __floats2half2_rn(v.z, v.w);
    uint2 o;
    o.x = *(uint32_t*)&h0;
    o.y = *(uint32_t*)&h1;
    ((uint2*)dst)[j] = o;
}

// ==================== HMMA fp16 GEMM (main projections) =====================
__device__ __forceinline__ void gemm_load_stage(uint32_t base, const __half* as,
                                                const __half* ws, int K, int tid) {
#pragma unroll
    for (int i = 0; i < 4; ++i) {
        int idx = i * 256 + tid;
        int row = idx >> 3, c = idx & 7;
        uint32_t off = (uint32_t)(row * 128 + ((c * 16) ^ ((row & 7) << 4)));
        cp_async16(base + off, as + (size_t)row * K + c * 8);
    }
    const uint32_t stA = BM * BK * 2;
#pragma unroll
    for (int i = 0; i < 4; ++i) {
        int idx = i * 256 + tid;
        int row = idx >> 3, c = idx & 7;
        uint32_t off = (uint32_t)(row * 128 + ((c * 16) ^ ((row & 7) << 4)));
        cp_async16(base + stA + off, ws + (size_t)row * K + c * 8);
    }
}

// EPI: 1 = fp32 out + bias(col) + fp32 residual, row-major C (M x Nn)
//      4 = fp16 out + bias(row),  C written as (B, D, L): row = d, col = m
template <int EPI>
__global__ void __launch_bounds__(256)
hgemm_kernel(const __half* __restrict__ A, const __half* __restrict__ W,
             const float* __restrict__ bias, const float* __restrict__ R,
             void* __restrict__ Cv, int M, int Nn, int K) {
    extern __shared__ __align__(1024) char smem[];
    const uint32_t sb = smem_u32(smem);
    const int tid = threadIdx.x;
    const int lane = tid & 31;
    const int wid = tid >> 5;
    const int wm = (wid & 3) * 32;
    const int wn = (wid >> 2) * 64;
    const int bx = blockIdx.x, by = blockIdx.y;

    const uint32_t stA = BM * BK * 2;
    const uint32_t stage_sz = 2 * stA;
    const int nk = K / BK;

    const __half* Ab = A + (size_t)(by * BM) * K;
    const __half* Wb = W + (size_t)(bx * BN) * K;

    gemm_load_stage(sb + 0 * stage_sz, Ab, Wb, K, tid);
    cp_commit();
    gemm_load_stage(sb + 1 * stage_sz, Ab + BK, Wb + BK, K, tid);
    cp_commit();

    float acc[2][8][4];
#pragma unroll
    for (int i = 0; i < 2; ++i)
#pragma unroll
        for (int j = 0; j < 8; ++j)
#pragma unroll
            for (int l = 0; l < 4; ++l) acc[i][j][l] = 0.0f;

    const int a_r  = lane & 15;
    const int a_kb = (lane >> 4) * 16;
    const int b_r  = ((lane >> 4) * 8) + (lane & 7);
    const int b_kb = ((lane >> 3) & 1) * 16;

    for (int kt = 0; kt < nk; ++kt) {
        cp_wait<STAGES - 2>();
        __syncthreads();

        if (kt + 2 < nk) {
            gemm_load_stage(sb + ((kt + 2) % STAGES) * stage_sz,
                            Ab + (kt + 2) * BK, Wb + (kt + 2) * BK, K, tid);
        }
        cp_commit();

        const uint32_t baseA = sb + (kt % STAGES) * stage_sz;
        const uint32_t baseB = baseA + stA;

#pragma unroll
        for (int ks = 0; ks < 4; ++ks) {
            const int kb0 = ks * 32;
            uint32_t a_frag[2][4];
#pragma unroll
            for (int mt = 0; mt < 2; ++mt) {
                int row = wm + mt * 16 + a_r;
                uint32_t addr = baseA + row * 128 + ((kb0 + a_kb) ^ ((row & 7) << 4));
                ldsm_x4(a_frag[mt], addr);
            }
            uint32_t b_frag[4][4];
#pragma unroll
            for (int nb4 = 0; nb4 < 4; ++nb4) {
                int row = wn + nb4 * 16 + b_r;
                uint32_t addr = baseB + row * 128 + ((kb0 + b_kb) ^ ((row & 7) << 4));
                ldsm_x4(b_frag[nb4], addr);
            }
#pragma unroll
            for (int mt = 0; mt < 2; ++mt)
#pragma unroll
                for (int nb = 0; nb < 8; ++nb) {
                    uint32_t b0 = b_frag[nb >> 1][(nb & 1) * 2 + 0];
                    uint32_t b1 = b_frag[nb >> 1][(nb & 1) * 2 + 1];
                    mma16816(acc[mt][nb], a_frag[mt], b0, b1);
                }
        }
    }

    const int gr = lane >> 2;
    const int gc = (lane & 3) * 2;

    if (EPI == 1) {
        float* C = (float*)Cv;
#pragma unroll
        for (int mt = 0; mt < 2; ++mt) {
#pragma unroll
            for (int nb = 0; nb < 8; ++nb) {
                int row0 = by * BM + wm + mt * 16 + gr;
                int col  = bx * BN + wn + nb * 8 + gc;
                float2 bs = *(const float2*)&bias[col];
                float2 v0, v1;
                v0.x = acc[mt][nb][0] + bs.x;
                v0.y = acc[mt][nb][1] + bs.y;
                v1.x = acc[mt][nb][2] + bs.x;
                v1.y = acc[mt][nb][3] + bs.y;
                float2 r0 = *(const float2*)&R[(size_t)row0 * Nn + col];
                float2 r1 = *(const float2*)&R[(size_t)(row0 + 8) * Nn + col];
                v0.x += r0.x; v0.y += r0.y;
                v1.x += r1.x; v1.y += r1.y;
                *(float2*)&C[(size_t)row0 * Nn + col] = v0;
                *(float2*)&C[(size_t)(row0 + 8) * Nn + col] = v1;
            }
        }
    } else {
        // EPI == 4: rows = channels d, cols = m (one batch per tile).
        __half* C = (__half*)Cv;
        const int b  = (bx * BN) / Lq;
        const int l0 = (bx * BN) % Lq;
#pragma unroll
        for (int mt = 0; mt < 2; ++mt) {
            int d0 = by * BM + wm + mt * 16 + gr;
            float bs0 = bias[d0];
            float bs1 = bias[d0 + 8];
            __half* r0p = C + ((size_t)(b * Dq + d0)) * Lq + l0;
            __half* r1p = C + ((size_t)(b * Dq + d0 + 8)) * Lq + l0;
#pragma unroll
            for (int nb = 0; nb < 8; ++nb) {
                int cl = wn + nb * 8 + gc;
                *(__half2*)&r0p[cl] = __floats2half2_rn(acc[mt][nb][0] + bs0,
                                                        acc[mt][nb][1] + bs0);
                *(__half2*)&r1p[cl] = __floats2half2_rn(acc[mt][nb][2] + bs1,
                                                        acc[mt][nb][3] + bs1);
            }
        }
    }
}

// ==================== chunked SSM kernel (prep fused in) =====================
#define SM_KT  0
#define SM_P   8192
#define SM_SO  16384
#define SM_U   24576
#define SM_SH  40960
#define SM_AGG 57344
#define SM_WT  74240
#define SM_KS  74496
#define AGG_STRIDE 132
#define SM_TOTAL_S4 74752

__device__ __forceinline__ void small_gemm(uint32_t Abase, uint32_t Bbase,
                                           float acc[8][4], int wmi, int wn, int lane) {
    const int a_r  = lane & 15;
    const int a_kb = (lane >> 4) * 16;
    const int b_r  = ((lane >> 4) * 8) + (lane & 7);
    const int b_kb = ((lane >> 3) & 1) * 16;
#pragma unroll
    for (int ks = 0; ks < 4; ++ks) {
        const int kb0 = ks * 32;
        uint32_t a_frag[4];
        {
            int row = wmi + a_r;
            ldsm_x4(a_frag, Abase + row * 128 + ((kb0 + a_kb) ^ ((row & 7) << 4)));
        }
        uint32_t b_frag[4][4];
#pragma unroll
        for (int nb4 = 0; nb4 < 4; ++nb4) {
            int row = wn + nb4 * 16 + b_r;
            ldsm_x4(b_frag[nb4], Bbase + row * 128 + ((kb0 + b_kb) ^ ((row & 7) << 4)));
        }
#pragma unroll
        for (int nb = 0; nb < 8; ++nb)
            mma16816(acc[nb], a_frag,
                     b_frag[nb >> 1][(nb & 1) * 2 + 0],
                     b_frag[nb >> 1][(nb & 1) * 2 + 1]);
    }
}

// half store at swizzled (row, col) in a 128B-row tile
__device__ __forceinline__ void st_sw(char* smem, uint32_t base, int row, int col, float v) {
    *(__half*)(smem + base + row * 128 + ((col * 2) ^ ((row & 7) << 4))) = __float2half(v);
}

__global__ void __launch_bounds__(256, 3)
s4chunk_kernel(const __half* __restrict__ Ut,
               const float* __restrict__ log_dt, const float* __restrict__ Cc,
               const float* __restrict__ log_A_real, const float* __restrict__ A_imag,
               const float* __restrict__ dskip, __half* __restrict__ Yt) {
    extern __shared__ __align__(1024) char smem[];
    const uint32_t sb = smem_u32(smem);
    const int d = blockIdx.x;
    const int tid = threadIdx.x;
    const int lane = tid & 31;
    const int wid = tid >> 5;
    const int wmi = (wid & 3) * 16;
    const int wn  = (wid >> 2) * 64;

    __half* AGG16 = (__half*)(smem + SM_AGG);   // [64][132] fp16
    __half* Ysm   = (__half*)(smem + SM_AGG);   // reused: [128][64] fp16
    float*  WT    = (float*)(smem + SM_WT);     // [32][2]
    float*  KS    = (float*)(smem + SM_KS);     // [64]

    // ---- kick off U tile load first (overlaps prep math) ----
#pragma unroll
    for (int i = 0; i < 4; ++i) {
        int e = i * 256 + tid;
        int row = e >> 3, c8 = e & 7;
        int b = row >> 4, cl = row & 15;
        uint32_t off = row * 128 + ((c8 * 16) ^ ((row & 7) << 4));
        cp_async16(sb + SM_U + off,
                   Ut + ((size_t)(b * Dq + d)) * Lq + cl * 64 + c8 * 8);
    }
    cp_commit();

    // ---- fused prep: each warp computes 8 powers (p0 = wid*8) ----
    {
        const int n = lane;
        const int idx = d * Nq + n;
        float dt   = expf(log_dt[d]);
        float a_re = -expf(log_A_real[idx]);
        float a_im = A_imag[idx];
        float ex   = expf(a_re * dt);
        float wre  = ex * cosf(a_im * dt);
        float wim  = ex * sinf(a_im * dt);
        float n_re = wre - 1.0f, n_im = wim;
        float den  = a_re * a_re + a_im * a_im;
        float f_re = (n_re * a_re + n_im * a_im) / den;
        float f_im = (n_im * a_re - n_re * a_im) / den;
        float C_re = Cc[idx * 2 + 0];
        float C_im = Cc[idx * 2 + 1];
        float cre  = 2.0f * (C_re * f_re - C_im * f_im);
        float cim  = 2.0f * (C_re * f_im + C_im * f_re);

        // w^(p0) via binary exponentiation
        int e = wid * 8;
        float pr = 1.0f, pi = 0.0f, br = wre, bi = wim;
        while (e) {
            if (e & 1) {
                float t = pr * br - pi * bi;
                pi = pr * bi + pi * br;
                pr = t;
            }
            float t2 = br * br - bi * bi;
            bi = 2.0f * br * bi;
            br = t2;
            e >>= 1;
        }
        float qr = cre * pr - cim * pi;
        float qi = cre * pi + cim * pr;

#pragma unroll
        for (int j = 0; j < 8; ++j) {
            int p = wid * 8 + j;
            st_sw(smem, SM_P, n, 63 - p, pr);
            st_sw(smem, SM_P, 32 + n, 63 - p, pi);
            float s = qr;
#pragma unroll
            for (int off = 16; off; off >>= 1)
                s += __shfl_xor_sync(0xffffffffu, s, off);
            if (n == 0) KS[p] = s;
            if (p >= 1) {
                st_sw(smem, SM_SO, p - 1, n, qr);
                st_sw(smem, SM_SO, p - 1, 32 + n, -qi);
            }
            float npr = pr * wre - pi * wim;
            float npi = pr * wim + pi * wre;
            pr = npr; pi = npi;
            float nqr = qr * wre - qi * wim;
            float nqi = qr * wim + qi * wre;
            qr = nqr; qi = nqi;
        }
        if (wid == 7) {
            st_sw(smem, SM_SO, 63, n, qr);
            st_sw(smem, SM_SO, 63, 32 + n, -qi);
            WT[n * 2 + 0] = pr;
            WT[n * 2 + 1] = pi;
        }
    }
    __syncthreads();

    // ---- KT fill: KT[i][j] = k[i-j] (j<=i) + skip on diagonal ----
    {
        const float skip = dskip[d];
        for (int ee = tid; ee < 4096; ee += 256) {
            int i = ee >> 6, j = ee & 63;
            float v = (j <= i ? KS[i - j] : 0.0f) + (i == j ? skip : 0.0f);
            st_sw(smem, SM_KT, i, j, v);
        }
    }
    cp_wait<0>();
    __syncthreads();

    const int gr = lane >> 2;
    const int gc = (lane & 3) * 2;

    // GEMM1: AGG = P @ U^T  (fp16 staging, padded stride)
    {
        float agg[8][4];
#pragma unroll
        for (int j = 0; j < 8; ++j)
#pragma unroll
            for (int l = 0; l < 4; ++l) agg[j][l] = 0.0f;
        small_gemm(sb + SM_P, sb + SM_U, agg, wmi, wn, lane);
#pragma unroll
        for (int nb = 0; nb < 8; ++nb) {
            int col = wn + nb * 8 + gc;
            *(__half2*)&AGG16[(wmi + gr) * AGG_STRIDE + col] =
                __floats2half2_rn(agg[nb][0], agg[nb][1]);
            *(__half2*)&AGG16[(wmi + gr + 8) * AGG_STRIDE + col] =
                __floats2half2_rn(agg[nb][2], agg[nb][3]);
        }
    }
    __syncthreads();

    // boundary-state recurrence (fp32 state, fp16 AGG reads)
    {
        int n = tid & 31, b = tid >> 5;
        float wtr = WT[n * 2 + 0];
        float wti = WT[n * 2 + 1];
        float Er = 0.0f, Ei = 0.0f;
        for (int cl = 0; cl < 16; ++cl) {
            int c = b * 16 + cl;
            *(__half*)(smem + SM_SH + c * 128 + ((n * 2) ^ ((c & 7) << 4))) = __float2half(Er);
            *(__half*)(smem + SM_SH + c * 128 + (((32 + n) * 2) ^ ((c & 7) << 4))) = __float2half(Ei);
            float ar = __half2float(AGG16[n * AGG_STRIDE + c]);
            float ai = __half2float(AGG16[(32 + n) * AGG_STRIDE + c]);
            float nEr = fmaf(wtr, Er, fmaf(-wti, Ei, ar));
            float nEi = fmaf(wtr, Ei, fmaf(wti, Er, ai));
            Er = nEr; Ei = nEi;
        }
    }
    __syncthreads();

    // GEMM2 + GEMM3: Y = KT @ U^T + SO @ S_h
    float acc[8][4];
#pragma unroll
    for (int j = 0; j < 8; ++j)
#pragma unroll
        for (int l = 0; l < 4; ++l) acc[j][l] = 0.0f;
    small_gemm(sb + SM_KT, sb + SM_U,  acc, wmi, wn, lane);
    small_gemm(sb + SM_SO, sb + SM_SH, acc, wmi, wn, lane);

    // GELU directly on accumulator, stage to Ysm
#pragma unroll
    for (int nb = 0; nb < 8; ++nb) {
#pragma unroll
        for (int q = 0; q < 4; ++q) {
            int i = wmi + gr + (q >> 1) * 8;
            int c = wn + nb * 8 + gc + (q & 1);
            float v = acc[nb][q];
            float g = 0.5f * v * (1.0f + erff(v * 0.70710678118654752f));
            Ysm[c * 64 + i] = __float2half(g);
        }
    }
    __syncthreads();

#pragma unroll
    for (int it = 0; it < 16; ++it) {
        int e2 = it * 256 + tid;
        int h = e2 * 2;
        int c = h >> 6, i = h & 63;
        __half2 v = __halves2half2(Ysm[c * 64 + i], Ysm[c * 64 + i + 1]);
        int b = c >> 4, cl = c & 15;
        *(__half2*)&Yt[((size_t)(b * Dq + d)) * Lq + cl * 64 + i] = v;
    }
}

// ==================== GLU-fused HMMA GEMM (A from (B,D,L) layout) ============
__device__ __forceinline__ void glu_load_stage(uint32_t base, const __half* aYb,
                                               int d0, const __half* wa,
                                               const __half* wg, int K, int tid) {
#pragma unroll
    for (int i = 0; i < 4; ++i) {
        int idx = i * 256 + tid;
        int row = idx >> 4, c = idx & 15;
        uint32_t off = (uint32_t)(row * 256 + ((c * 16) ^ ((row & 7) << 4)));
        cp_async16(base + off, aYb + (size_t)(d0 + row) * Lq + c * 8);
    }
    const uint32_t stA = BM * BK * 2;   // 16KB
#pragma unroll
    for (int i = 0; i < 2; ++i) {
        int idx = i * 256 + tid;
        int row = idx >> 3, c = idx & 7;
        uint32_t off = (uint32_t)(row * 128 + ((c * 16) ^ ((row & 7) << 4)));
        cp_async16(base + stA + off, wa + (size_t)row * K + c * 8);
    }
    const uint32_t stB = 64 * BK * 2;   // 8KB
#pragma unroll
    for (int i = 0; i < 2; ++i) {
        int idx = i * 256 + tid;
        int row = idx >> 3, c = idx & 7;
        uint32_t off = (uint32_t)(row * 128 + ((c * 16) ^ ((row & 7) << 4)));
        cp_async16(base + stA + stB + off, wg + (size_t)row * K + c * 8);
    }
}

__global__ void __launch_bounds__(256)
hglu_kernel(const __half* __restrict__ Yt, const __half* __restrict__ W,
            const float* __restrict__ bias, __half* __restrict__ YG, int K) {
    extern __shared__ __align__(1024) char smem[];
    const uint32_t sb = smem_u32(smem);
    const int tid = threadIdx.x;
    const int lane = tid & 31;
    const int wid = tid >> 5;
    const int wm = (wid & 3) * 32;
    const int wn = (wid >> 2) * 32;
    const int bx = blockIdx.x, by = blockIdx.y;

    const uint32_t stA = BM * BK * 2;
    const uint32_t stB = 64 * BK * 2;
    const uint32_t stage_sz = stA + 2 * stB;
    const int nk = K / BK;

    const int bb = (by * BM) / Lq;
    const int l0 = (by * BM) % Lq;
    const __half* aYb = Yt + ((size_t)bb * Dq) * Lq + l0;
    const __half* Wa = W + (size_t)(bx * 64) * K;
    const __half* Wg = W + (size_t)(Dq + bx * 64) * K;

    glu_load_stage(sb + 0 * stage_sz, aYb, 0,  Wa,      Wg,      K, tid);
    cp_commit();
    glu_load_stage(sb + 1 * stage_sz, aYb, BK, Wa + BK, Wg + BK, K, tid);
    cp_commit();

    float acc[2][2][4][4];
#pragma unroll
    for (int i = 0; i < 2; ++i)
#pragma unroll
        for (int h = 0; h < 2; ++h)
#pragma unroll
            for (int j = 0; j < 4; ++j)
#pragma unroll
                for (int l = 0; l < 4; ++l) acc[i][h][j][l] = 0.0f;

    const int at_kr = (lane & 7) + ((lane >> 4) << 3);
    const int at_mc = ((lane >> 3) & 1) << 4;
    const int b_r  = ((lane >> 4) * 8) + (lane & 7);
    const int b_kb = ((lane >> 3) & 1) * 16;

    for (int kt = 0; kt < nk; ++kt) {
        cp_wait<STAGES - 2>();
        __syncthreads();

        if (kt + 2 < nk) {
            glu_load_stage(sb + ((kt + 2) % STAGES) * stage_sz,
                           aYb, (kt + 2) * BK, Wa + (kt + 2) * BK,
                           Wg + (kt + 2) * BK, K, tid);
        }
        cp_commit();

        const uint32_t baseA = sb + (kt % STAGES) * stage_sz;
        const uint32_t baseB = baseA + stA;

#pragma unroll
        for (int ks = 0; ks < 4; ++ks) {
            const int kb0 = ks * 32;
            uint32_t a_frag[2][4];
#pragma unroll
            for (int mt = 0; mt < 2; ++mt) {
                int krow = ks * 16 + at_kr;
                int colb = (wm + mt * 16) * 2 + at_mc;
                uint32_t addr = baseA + krow * 256 + (colb ^ ((krow & 7) << 4));
                ldsm_x4_trans(a_frag[mt], addr);
            }
            uint32_t b_frag[2][2][4];
#pragma unroll
            for (int h = 0; h < 2; ++h)
#pragma unroll
                for (int nb4 = 0; nb4 < 2; ++nb4) {
                    int row = wn + nb4 * 16 + b_r;
                    uint32_t addr = baseB + h * stB + row * 128
                                  + ((kb0 + b_kb) ^ ((row & 7) << 4));
                    ldsm_x4(b_frag[h][nb4], addr);
                }
#pragma unroll
            for (int mt = 0; mt < 2; ++mt)
#pragma unroll
                for (int h = 0; h < 2; ++h)
#pragma unroll
                    for (int nb = 0; nb < 4; ++nb) {
                        uint32_t b0 = b_frag[h][nb >> 1][(nb & 1) * 2 + 0];
                        uint32_t b1 = b_frag[h][nb >> 1][(nb & 1) * 2 + 1];
                        mma16816(acc[mt][h][nb], a_frag[mt], b0, b1);
                    }
        }
    }

    const int gr = lane >> 2;
    const int gc = (lane & 3) * 2;
#pragma unroll
    for (int mt = 0; mt < 2; ++mt) {
#pragma unroll
        for (int nb = 0; nb < 4; ++nb) {
            int row0 = by * BM + wm + mt * 16 + gr;
            int col  = bx * 64 + wn + nb * 8 + gc;
            float2 ba = *(const float2*)&bias[col];
            float2 bg = *(const float2*)&bias[Dq + col];
#pragma unroll
            for (int rr = 0; rr < 2; ++rr) {
                int row = row0 + rr * 8;
                float av0 = acc[mt][0][nb][rr * 2 + 0] + ba.x;
                float av1 = acc[mt][0][nb][rr * 2 + 1] + ba.y;
                float gv0 = acc[mt][1][nb][rr * 2 + 0] + bg.x;
                float gv1 = acc[mt][1][nb][rr * 2 + 1] + bg.y;
                float o0 = av0 / (1.0f + __expf(-gv0));
                float o1 = av1 / (1.0f + __expf(-gv1));
                *(__half2*)&YG[(size_t)row * Dq + col] = __floats2half2_rn(o0, o1);
            }
        }
    }
}

// ---------------- launch --------------------------------------------------
extern "C" void kernel_launch(void* const* d_in, const int* in_sizes, int n_in,
                              void* d_out, int out_size) {
    const float* x          = (const float*)d_in[0];
    const float* in_W       = (const float*)d_in[1];
    const float* in_b       = (const float*)d_in[2];
    const float* log_dt     = (const float*)d_in[3];
    const float* Cc         = (const float*)d_in[4];
    const float* log_A_real = (const float*)d_in[5];
    const float* A_imag     = (const float*)d_in[6];
    const float* D_skip     = (const float*)d_in[7];
    const float* glu_W      = (const float*)d_in[8];
    const float* glu_b      = (const float*)d_in[9];
    const float* out_W      = (const float*)d_in[10];
    const float* out_b      = (const float*)d_in[11];
    float* out = (float*)d_out;

    __half *xh, *ut, *yt, *ygh, *wih, *wgh, *woh;
    cudaGetSymbolAddress((void**)&xh,  g_xh);
    cudaGetSymbolAddress((void**)&ut,  g_ut);
    cudaGetSymbolAddress((void**)&yt,  g_yt);
    cudaGetSymbolAddress((void**)&ygh, g_ygh);
    cudaGetSymbolAddress((void**)&wih, g_wih);
    cudaGetSymbolAddress((void**)&wgh, g_wgh);
    cudaGetSymbolAddress((void**)&woh, g_woh);

    const int SMEM_SZ = STAGES * 2 * BM * BK * 2;   // 96KB
    cudaFuncSetAttribute(hgemm_kernel<1>, cudaFuncAttributeMaxDynamicSharedMemorySize, SMEM_SZ);
    cudaFuncSetAttribute(hgemm_kernel<4>, cudaFuncAttributeMaxDynamicSharedMemorySize, SMEM_SZ);
    cudaFuncSetAttribute(hglu_kernel, cudaFuncAttributeMaxDynamicSharedMemorySize, SMEM_SZ);
    cudaFuncSetAttribute(s4chunk_kernel, cudaFuncAttributeMaxDynamicSharedMemorySize, SM_TOTAL_S4);

    // 1) fp16 conversions
    {
        int total4 = N4X + N4I + N4G + N4O;
        cvt_all_kernel<<<(total4 + 255) / 256, 256>>>(x, in_W, glu_W, out_W,
                                                      xh, wih, wgh, woh);
    }

    // 2) in_proj computed transposed: ut[d][m] = in_W @ x^T, written as (B, D, L)
    {
        dim3 grid(Mq / BN, Dq / BM);
        hgemm_kernel<4><<<grid, 256, SMEM_SZ>>>(wih, xh, in_b, nullptr, ut, Dq, Mq, Dq);
    }

    // 3) chunked SSM (prep fused) + skip + GELU -> Yt (B, D, L)
    s4chunk_kernel<<<Dq, 256, SM_TOTAL_S4>>>(ut, log_dt, Cc, log_A_real, A_imag,
                                             D_skip, yt);

    // 4) GLU GEMM (A read transposed from yt) fused with a*sigmoid(g) -> fp16
    {
        dim3 grid(Dq / 64, Mq / BM);
        hglu_kernel<<<grid, 256, SMEM_SZ>>>(yt, wgh, glu_b, ygh, Dq);
    }

    // 5) out_proj + fp32 residual
    {
        dim3 grid(Dq / BN, Mq / BM);
        hgemm_kernel<1><<<grid, 256, SMEM_SZ>>>(ygh, woh, out_b, x, out, Mq, Dq, Dq);
    }
}

// round 17
// speedup vs baseline: 1.0564x; 1.0072x over previous
#include <cuda_runtime.h>
#include <cuda_fp16.h>
#include <math.h>
#include <cstdint>

// Problem constants
#define Bq   8
#define Lq   1024
#define Dq   1024
#define Nq   32
#define Mq   (Bq * Lq)          // 8192 rows

#define BM 128
#define BN 128
#define BK 64
#define STAGES 3

// ---------------- scratch (device globals; no allocations allowed) ----------
__device__ __align__(128) __half g_xh [(size_t)Mq * Dq];       // x fp16
__device__ __align__(128) __half g_ut [(size_t)Mq * Dq];       // in_proj out (B, D, L)
__device__ __align__(128) __half g_yt [(size_t)Mq * Dq];       // SSM out (B, D, L)
__device__ __align__(128) __half g_ygh[(size_t)Mq * Dq];       // GLU out fp16
__device__ __align__(128) __half g_wih[(size_t)Dq * Dq];       // in_W fp16
__device__ __align__(128) __half g_wgh[(size_t)2 * Dq * Dq];   // glu_W fp16
__device__ __align__(128) __half g_woh[(size_t)Dq * Dq];       // out_W fp16

// ==================== PTX helpers (baseline sm_80+ features only) ===========
__device__ __forceinline__ uint32_t smem_u32(const void* p) {
    return (uint32_t)__cvta_generic_to_shared(p);
}
__device__ __forceinline__ void cp_async16(uint32_t dst, const void* src) {
    asm volatile("cp.async.cg.shared.global [%0], [%1], 16;" :: "r"(dst), "l"(src));
}
__device__ __forceinline__ void cp_commit() {
    asm volatile("cp.async.commit_group;" ::: "memory");
}
template <int N>
__device__ __forceinline__ void cp_wait() {
    asm volatile("cp.async.wait_group %0;" :: "n"(N) : "memory");
}
__device__ __forceinline__ void ldsm_x4(uint32_t* r, uint32_t addr) {
    asm volatile("ldmatrix.sync.aligned.m8n8.x4.shared.b16 {%0,%1,%2,%3}, [%4];"
                 : "=r"(r[0]), "=r"(r[1]), "=r"(r[2]), "=r"(r[3]) : "r"(addr));
}
__device__ __forceinline__ void ldsm_x4_trans(uint32_t* r, uint32_t addr) {
    asm volatile("ldmatrix.sync.aligned.m8n8.x4.trans.shared.b16 {%0,%1,%2,%3}, [%4];"
                 : "=r"(r[0]), "=r"(r[1]), "=r"(r[2]), "=r"(r[3]) : "r"(addr));
}
__device__ __forceinline__ void mma16816(float* c, const uint32_t* a, uint32_t b0, uint32_t b1) {
    asm volatile("mma.sync.aligned.m16n8k16.row.col.f32.f16.f16.f32 "
                 "{%0,%1,%2,%3}, {%4,%5,%6,%7}, {%8,%9}, {%0,%1,%2,%3};"
                 : "+f"(c[0]), "+f"(c[1]), "+f"(c[2]), "+f"(c[3])
                 : "r"(a[0]), "r"(a[1]), "r"(a[2]), "r"(a[3]), "r"(b0), "r"(b1));
}

// ---------------- fp32 -> fp16 conversion (all tensors in one launch) -------
#define N4X (Mq * Dq / 4)
#define N4I (Dq * Dq / 4)
#define N4G (2 * Dq * Dq / 4)
#define N4O (Dq * Dq / 4)
__global__ void cvt_all_kernel(const float* __restrict__ x,
                               const float* __restrict__ wi,
                               const float* __restrict__ wg,
                               const float* __restrict__ wo,
                               __half* __restrict__ xh, __half* __restrict__ wih,
                               __half* __restrict__ wgh, __half* __restrict__ woh) {
    int i = blockIdx.x * blockDim.x + threadIdx.x;
    const float* src;
    __half* dst;
    int j = i;
    if (j < N4X) { src = x; dst = xh; }
    else if ((j -= N4X) < N4I) { src = wi; dst = wih; }
    else if ((j -= N4I) < N4G) { src = wg; dst = wgh; }
    else if ((j -= N4G) < N4O) { src = wo; dst = woh; }
    else return;
    float4 v = ((const float4*)src)[j];
    __half2 h0 = __floats2half2_rn(v.x, v.y);
    __half2 h1 = __floats2half2_rn(v.z, v.w);
    uint2 o;
    o.x = *(uint32_t*)&h0;
    o.y = *(uint32_t*)&h1;
    ((uint2*)dst)[j] = o;
}

// ==================== HMMA fp16 GEMM (main projections) =====================
__device__ __forceinline__ void gemm_load_stage(uint32_t base, const __half* as,
                                                const __half* ws, int K, int tid) {
#pragma unroll
    for (int i = 0; i < 4; ++i) {
        int idx = i * 256 + tid;
        int row = idx >> 3, c = idx & 7;
        uint32_t off = (uint32_t)(row * 128 + ((c * 16) ^ ((row & 7) << 4)));
        cp_async16(base + off, as + (size_t)row * K + c * 8);
    }
    const uint32_t stA = BM * BK * 2;
#pragma unroll
    for (int i = 0; i < 4; ++i) {
        int idx = i * 256 + tid;
        int row = idx >> 3, c = idx & 7;
        uint32_t off = (uint32_t)(row * 128 + ((c * 16) ^ ((row & 7) << 4)));
        cp_async16(base + stA + off, ws + (size_t)row * K + c * 8);
    }
}

// EPI: 1 = fp32 out + bias(col) + fp32 residual, row-major C (M x Nn)
//      4 = fp16 out + bias(row),  C written as (B, D, L): row = d, col = m
template <int EPI>
__global__ void __launch_bounds__(256)
hgemm_kernel(const __half* __restrict__ A, const __half* __restrict__ W,
             const float* __restrict__ bias, const float* __restrict__ R,
             void* __restrict__ Cv, int M, int Nn, int K) {
    extern __shared__ __align__(1024) char smem[];
    const uint32_t sb = smem_u32(smem);
    const int tid = threadIdx.x;
    const int lane = tid & 31;
    const int wid = tid >> 5;
    const int wm = (wid & 3) * 32;
    const int wn = (wid >> 2) * 64;
    const int bx = blockIdx.x, by = blockIdx.y;

    const uint32_t stA = BM * BK * 2;
    const uint32_t stage_sz = 2 * stA;
    const int nk = K / BK;

    const __half* Ab = A + (size_t)(by * BM) * K;
    const __half* Wb = W + (size_t)(bx * BN) * K;

    gemm_load_stage(sb + 0 * stage_sz, Ab, Wb, K, tid);
    cp_commit();
    gemm_load_stage(sb + 1 * stage_sz, Ab + BK, Wb + BK, K, tid);
    cp_commit();

    float acc[2][8][4];
#pragma unroll
    for (int i = 0; i < 2; ++i)
#pragma unroll
        for (int j = 0; j < 8; ++j)
#pragma unroll
            for (int l = 0; l < 4; ++l) acc[i][j][l] = 0.0f;

    const int a_r  = lane & 15;
    const int a_kb = (lane >> 4) * 16;
    const int b_r  = ((lane >> 4) * 8) + (lane & 7);
    const int b_kb = ((lane >> 3) & 1) * 16;

    for (int kt = 0; kt < nk; ++kt) {
        cp_wait<STAGES - 2>();
        __syncthreads();

        if (kt + 2 < nk) {
            gemm_load_stage(sb + ((kt + 2) % STAGES) * stage_sz,
                            Ab + (kt + 2) * BK, Wb + (kt + 2) * BK, K, tid);
        }
        cp_commit();

        const uint32_t baseA = sb + (kt % STAGES) * stage_sz;
        const uint32_t baseB = baseA + stA;

#pragma unroll
        for (int ks = 0; ks < 4; ++ks) {
            const int kb0 = ks * 32;
            uint32_t a_frag[2][4];
#pragma unroll
            for (int mt = 0; mt < 2; ++mt) {
                int row = wm + mt * 16 + a_r;
                uint32_t addr = baseA + row * 128 + ((kb0 + a_kb) ^ ((row & 7) << 4));
                ldsm_x4(a_frag[mt], addr);
            }
            uint32_t b_frag[4][4];
#pragma unroll
            for (int nb4 = 0; nb4 < 4; ++nb4) {
                int row = wn + nb4 * 16 + b_r;
                uint32_t addr = baseB + row * 128 + ((kb0 + b_kb) ^ ((row & 7) << 4));
                ldsm_x4(b_frag[nb4], addr);
            }
#pragma unroll
            for (int mt = 0; mt < 2; ++mt)
#pragma unroll
                for (int nb = 0; nb < 8; ++nb) {
                    uint32_t b0 = b_frag[nb >> 1][(nb & 1) * 2 + 0];
                    uint32_t b1 = b_frag[nb >> 1][(nb & 1) * 2 + 1];
                    mma16816(acc[mt][nb], a_frag[mt], b0, b1);
                }
        }
    }

    const int gr = lane >> 2;
    const int gc = (lane & 3) * 2;

    if (EPI == 1) {
        float* C = (float*)Cv;
#pragma unroll
        for (int mt = 0; mt < 2; ++mt) {
#pragma unroll
            for (int nb = 0; nb < 8; ++nb) {
                int row0 = by * BM + wm + mt * 16 + gr;
                int col  = bx * BN + wn + nb * 8 + gc;
                float2 bs = *(const float2*)&bias[col];
                float2 v0, v1;
                v0.x = acc[mt][nb][0] + bs.x;
                v0.y = acc[mt][nb][1] + bs.y;
                v1.x = acc[mt][nb][2] + bs.x;
                v1.y = acc[mt][nb][3] + bs.y;
                float2 r0 = *(const float2*)&R[(size_t)row0 * Nn + col];
                float2 r1 = *(const float2*)&R[(size_t)(row0 + 8) * Nn + col];
                v0.x += r0.x; v0.y += r0.y;
                v1.x += r1.x; v1.y += r1.y;
                *(float2*)&C[(size_t)row0 * Nn + col] = v0;
                *(float2*)&C[(size_t)(row0 + 8) * Nn + col] = v1;
            }
        }
    } else {
        // EPI == 4: rows = channels d, cols = m (one batch per tile).
        __half* C = (__half*)Cv;
        const int b  = (bx * BN) / Lq;
        const int l0 = (bx * BN) % Lq;
#pragma unroll
        for (int mt = 0; mt < 2; ++mt) {
            int d0 = by * BM + wm + mt * 16 + gr;
            float bs0 = bias[d0];
            float bs1 = bias[d0 + 8];
            __half* r0p = C + ((size_t)(b * Dq + d0)) * Lq + l0;
            __half* r1p = C + ((size_t)(b * Dq + d0 + 8)) * Lq + l0;
#pragma unroll
            for (int nb = 0; nb < 8; ++nb) {
                int cl = wn + nb * 8 + gc;
                *(__half2*)&r0p[cl] = __floats2half2_rn(acc[mt][nb][0] + bs0,
                                                        acc[mt][nb][1] + bs0);
                *(__half2*)&r1p[cl] = __floats2half2_rn(acc[mt][nb][2] + bs1,
                                                        acc[mt][nb][3] + bs1);
            }
        }
    }
}

// ==================== chunked SSM kernel (prep fused in) =====================
#define SM_KT  0
#define SM_P   8192
#define SM_SO  16384
#define SM_U   24576
#define SM_SH  40960
#define SM_AGG 57344
#define SM_WT  74240
#define SM_KS  74496
#define AGG_STRIDE 132
#define SM_TOTAL_S4 74752

__device__ __forceinline__ void small_gemm(uint32_t Abase, uint32_t Bbase,
                                           float acc[8][4], int wmi, int wn, int lane) {
    const int a_r  = lane & 15;
    const int a_kb = (lane >> 4) * 16;
    const int b_r  = ((lane >> 4) * 8) + (lane & 7);
    const int b_kb = ((lane >> 3) & 1) * 16;
#pragma unroll
    for (int ks = 0; ks < 4; ++ks) {
        const int kb0 = ks * 32;
        uint32_t a_frag[4];
        {
            int row = wmi + a_r;
            ldsm_x4(a_frag, Abase + row * 128 + ((kb0 + a_kb) ^ ((row & 7) << 4)));
        }
        uint32_t b_frag[4][4];
#pragma unroll
        for (int nb4 = 0; nb4 < 4; ++nb4) {
            int row = wn + nb4 * 16 + b_r;
            ldsm_x4(b_frag[nb4], Bbase + row * 128 + ((kb0 + b_kb) ^ ((row & 7) << 4)));
        }
#pragma unroll
        for (int nb = 0; nb < 8; ++nb)
            mma16816(acc[nb], a_frag,
                     b_frag[nb >> 1][(nb & 1) * 2 + 0],
                     b_frag[nb >> 1][(nb & 1) * 2 + 1]);
    }
}

// half store at swizzled (row, col) in a 128B-row tile
__device__ __forceinline__ void st_sw(char* smem, uint32_t base, int row, int col, float v) {
    *(__half*)(smem + base + row * 128 + ((col * 2) ^ ((row & 7) << 4))) = __float2half(v);
}

__global__ void __launch_bounds__(256, 3)
s4chunk_kernel(const __half* __restrict__ Ut,
               const float* __restrict__ log_dt, const float* __restrict__ Cc,
               const float* __restrict__ log_A_real, const float* __restrict__ A_imag,
               const float* __restrict__ dskip, __half* __restrict__ Yt) {
    extern __shared__ __align__(1024) char smem[];
    const uint32_t sb = smem_u32(smem);
    const int d = blockIdx.x;
    const int tid = threadIdx.x;
    const int lane = tid & 31;
    const int wid = tid >> 5;
    const int wmi = (wid & 3) * 16;
    const int wn  = (wid >> 2) * 64;

    __half* AGG16 = (__half*)(smem + SM_AGG);   // [64][132] fp16
    __half* Ysm   = (__half*)(smem + SM_AGG);   // reused: [128][64] fp16
    float*  WT    = (float*)(smem + SM_WT);     // [32][2]
    float*  KS    = (float*)(smem + SM_KS);     // [64]

    // ---- kick off U tile load first (overlaps prep math) ----
#pragma unroll
    for (int i = 0; i < 4; ++i) {
        int e = i * 256 + tid;
        int row = e >> 3, c8 = e & 7;
        int b = row >> 4, cl = row & 15;
        uint32_t off = row * 128 + ((c8 * 16) ^ ((row & 7) << 4));
        cp_async16(sb + SM_U + off,
                   Ut + ((size_t)(b * Dq + d)) * Lq + cl * 64 + c8 * 8);
    }
    cp_commit();

    // ---- fused prep: each warp computes 8 powers (p0 = wid*8) ----
    {
        const int n = lane;
        const int idx = d * Nq + n;
        float dt   = expf(log_dt[d]);
        float a_re = -expf(log_A_real[idx]);
        float a_im = A_imag[idx];
        float ex   = expf(a_re * dt);
        float wre  = ex * cosf(a_im * dt);
        float wim  = ex * sinf(a_im * dt);
        float n_re = wre - 1.0f, n_im = wim;
        float den  = a_re * a_re + a_im * a_im;
        float f_re = (n_re * a_re + n_im * a_im) / den;
        float f_im = (n_im * a_re - n_re * a_im) / den;
        float C_re = Cc[idx * 2 + 0];
        float C_im = Cc[idx * 2 + 1];
        float cre  = 2.0f * (C_re * f_re - C_im * f_im);
        float cim  = 2.0f * (C_re * f_im + C_im * f_re);

        // w^(p0) via binary exponentiation
        int e = wid * 8;
        float pr = 1.0f, pi = 0.0f, br = wre, bi = wim;
        while (e) {
            if (e & 1) {
                float t = pr * br - pi * bi;
                pi = pr * bi + pi * br;
                pr = t;
            }
            float t2 = br * br - bi * bi;
            bi = 2.0f * br * bi;
            br = t2;
            e >>= 1;
        }
        float qr = cre * pr - cim * pi;
        float qi = cre * pi + cim * pr;

#pragma unroll
        for (int j = 0; j < 8; ++j) {
            int p = wid * 8 + j;
            st_sw(smem, SM_P, n, 63 - p, pr);
            st_sw(smem, SM_P, 32 + n, 63 - p, pi);
            float s = qr;
#pragma unroll
            for (int off = 16; off; off >>= 1)
                s += __shfl_xor_sync(0xffffffffu, s, off);
            if (n == 0) KS[p] = s;
            if (p >= 1) {
                st_sw(smem, SM_SO, p - 1, n, qr);
                st_sw(smem, SM_SO, p - 1, 32 + n, -qi);
            }
            float npr = pr * wre - pi * wim;
            float npi = pr * wim + pi * wre;
            pr = npr; pi = npi;
            float nqr = qr * wre - qi * wim;
            float nqi = qr * wim + qi * wre;
            qr = nqr; qi = nqi;
        }
        if (wid == 7) {
            st_sw(smem, SM_SO, 63, n, qr);
            st_sw(smem, SM_SO, 63, 32 + n, -qi);
            WT[n * 2 + 0] = pr;
            WT[n * 2 + 1] = pi;
        }
    }
    __syncthreads();

    // ---- KT fill: KT[i][j] = k[i-j] (j<=i) + skip on diagonal ----
    {
        const float skip = dskip[d];
        for (int ee = tid; ee < 4096; ee += 256) {
            int i = ee >> 6, j = ee & 63;
            float v = (j <= i ? KS[i - j] : 0.0f) + (i == j ? skip : 0.0f);
            st_sw(smem, SM_KT, i, j, v);
        }
    }
    cp_wait<0>();
    __syncthreads();

    const int gr = lane >> 2;
    const int gc = (lane & 3) * 2;

    // GEMM1: AGG = P @ U^T  (fp16 staging, padded stride)
    {
        float agg[8][4];
#pragma unroll
        for (int j = 0; j < 8; ++j)
#pragma unroll
            for (int l = 0; l < 4; ++l) agg[j][l] = 0.0f;
        small_gemm(sb + SM_P, sb + SM_U, agg, wmi, wn, lane);
#pragma unroll
        for (int nb = 0; nb < 8; ++nb) {
            int col = wn + nb * 8 + gc;
            *(__half2*)&AGG16[(wmi + gr) * AGG_STRIDE + col] =
                __floats2half2_rn(agg[nb][0], agg[nb][1]);
            *(__half2*)&AGG16[(wmi + gr + 8) * AGG_STRIDE + col] =
                __floats2half2_rn(agg[nb][2], agg[nb][3]);
        }
    }
    __syncthreads();

    // boundary-state recurrence (fp32 state, fp16 AGG reads)
    {
        int n = tid & 31, b = tid >> 5;
        float wtr = WT[n * 2 + 0];
        float wti = WT[n * 2 + 1];
        float Er = 0.0f, Ei = 0.0f;
        for (int cl = 0; cl < 16; ++cl) {
            int c = b * 16 + cl;
            *(__half*)(smem + SM_SH + c * 128 + ((n * 2) ^ ((c & 7) << 4))) = __float2half(Er);
            *(__half*)(smem + SM_SH + c * 128 + (((32 + n) * 2) ^ ((c & 7) << 4))) = __float2half(Ei);
            float ar = __half2float(AGG16[n * AGG_STRIDE + c]);
            float ai = __half2float(AGG16[(32 + n) * AGG_STRIDE + c]);
            float nEr = fmaf(wtr, Er, fmaf(-wti, Ei, ar));
            float nEi = fmaf(wtr, Ei, fmaf(wti, Er, ai));
            Er = nEr; Ei = nEi;
        }
    }
    __syncthreads();

    // GEMM2 + GEMM3: Y = KT @ U^T + SO @ S_h
    float acc[8][4];
#pragma unroll
    for (int j = 0; j < 8; ++j)
#pragma unroll
        for (int l = 0; l < 4; ++l) acc[j][l] = 0.0f;
    small_gemm(sb + SM_KT, sb + SM_U,  acc, wmi, wn, lane);
    small_gemm(sb + SM_SO, sb + SM_SH, acc, wmi, wn, lane);

    // GELU directly on accumulator, stage to Ysm
#pragma unroll
    for (int nb = 0; nb < 8; ++nb) {
#pragma unroll
        for (int q = 0; q < 4; ++q) {
            int i = wmi + gr + (q >> 1) * 8;
            int c = wn + nb * 8 + gc + (q & 1);
            float v = acc[nb][q];
            float g = 0.5f * v * (1.0f + erff(v * 0.70710678118654752f));
            Ysm[c * 64 + i] = __float2half(g);
        }
    }
    __syncthreads();

#pragma unroll
    for (int it = 0; it < 16; ++it) {
        int e2 = it * 256 + tid;
        int h = e2 * 2;
        int c = h >> 6, i = h & 63;
        __half2 v = __halves2half2(Ysm[c * 64 + i], Ysm[c * 64 + i + 1]);
        int b = c >> 4, cl = c & 15;
        *(__half2*)&Yt[((size_t)(b * Dq + d)) * Lq + cl * 64 + i] = v;
    }
}

// ==================== GLU-fused HMMA GEMM (A from (B,D,L) layout) ============
__device__ __forceinline__ void glu_load_stage(uint32_t base, const __half* aYb,
                                               int d0, const __half* wa,
                                               const __half* wg, int K, int tid) {
#pragma unroll
    for (int i = 0; i < 4; ++i) {
        int idx = i * 256 + tid;
        int row = idx >> 4, c = idx & 15;
        uint32_t off = (uint32_t)(row * 256 + ((c * 16) ^ ((row & 7) << 4)));
        cp_async16(base + off, aYb + (size_t)(d0 + row) * Lq + c * 8);
    }
    const uint32_t stA = BM * BK * 2;   // 16KB
#pragma unroll
    for (int i = 0; i < 2; ++i) {
        int idx = i * 256 + tid;
        int row = idx >> 3, c = idx & 7;
        uint32_t off = (uint32_t)(row * 128 + ((c * 16) ^ ((row & 7) << 4)));
        cp_async16(base + stA + off, wa + (size_t)row * K + c * 8);
    }
    const uint32_t stB = 64 * BK * 2;   // 8KB
#pragma unroll
    for (int i = 0; i < 2; ++i) {
        int idx = i * 256 + tid;
        int row = idx >> 3, c = idx & 7;
        uint32_t off = (uint32_t)(row * 128 + ((c * 16) ^ ((row & 7) << 4)));
        cp_async16(base + stA + stB + off, wg + (size_t)row * K + c * 8);
    }
}

__global__ void __launch_bounds__(256)
hglu_kernel(const __half* __restrict__ Yt, const __half* __restrict__ W,
            const float* __restrict__ bias, __half* __restrict__ YG, int K) {
    extern __shared__ __align__(1024) char smem[];
    const uint32_t sb = smem_u32(smem);
    const int tid = threadIdx.x;
    const int lane = tid & 31;
    const int wid = tid >> 5;
    const int wm = (wid & 3) * 32;
    const int wn = (wid >> 2) * 32;
    const int bx = blockIdx.x, by = blockIdx.y;

    const uint32_t stA = BM * BK * 2;
    const uint32_t stB = 64 * BK * 2;
    const uint32_t stage_sz = stA + 2 * stB;
    const int nk = K / BK;

    const int bb = (by * BM) / Lq;
    const int l0 = (by * BM) % Lq;
    const __half* aYb = Yt + ((size_t)bb * Dq) * Lq + l0;
    const __half* Wa = W + (size_t)(bx * 64) * K;
    const __half* Wg = W + (size_t)(Dq + bx * 64) * K;

    glu_load_stage(sb + 0 * stage_sz, aYb, 0,  Wa,      Wg,      K, tid);
    cp_commit();
    glu_load_stage(sb + 1 * stage_sz, aYb, BK, Wa + BK, Wg + BK, K, tid);
    cp_commit();

    float acc[2][2][4][4];
#pragma unroll
    for (int i = 0; i < 2; ++i)
#pragma unroll
        for (int h = 0; h < 2; ++h)
#pragma unroll
            for (int j = 0; j < 4; ++j)
#pragma unroll
                for (int l = 0; l < 4; ++l) acc[i][h][j][l] = 0.0f;

    const int at_kr = (lane & 7) + ((lane >> 4) << 3);
    const int at_mc = ((lane >> 3) & 1) << 4;
    const int b_r  = ((lane >> 4) * 8) + (lane & 7);
    const int b_kb = ((lane >> 3) & 1) * 16;

    for (int kt = 0; kt < nk; ++kt) {
        cp_wait<STAGES - 2>();
        __syncthreads();

        if (kt + 2 < nk) {
            glu_load_stage(sb + ((kt + 2) % STAGES) * stage_sz,
                           aYb, (kt + 2) * BK, Wa + (kt + 2) * BK,
                           Wg + (kt + 2) * BK, K, tid);
        }
        cp_commit();

        const uint32_t baseA = sb + (kt % STAGES) * stage_sz;
        const uint32_t baseB = baseA + stA;

#pragma unroll
        for (int ks = 0; ks < 4; ++ks) {
            const int kb0 = ks * 32;
            uint32_t a_frag[2][4];
#pragma unroll
            for (int mt = 0; mt < 2; ++mt) {
                int krow = ks * 16 + at_kr;
                int colb = (wm + mt * 16) * 2 + at_mc;
                uint32_t addr = baseA + krow * 256 + (colb ^ ((krow & 7) << 4));
                ldsm_x4_trans(a_frag[mt], addr);
            }
            uint32_t b_frag[2][2][4];
#pragma unroll
            for (int h = 0; h < 2; ++h)
#pragma unroll
                for (int nb4 = 0; nb4 < 2; ++nb4) {
                    int row = wn + nb4 * 16 + b_r;
                    uint32_t addr = baseB + h * stB + row * 128
                                  + ((kb0 + b_kb) ^ ((row & 7) << 4));
                    ldsm_x4(b_frag[h][nb4], addr);
                }
#pragma unroll
            for (int mt = 0; mt < 2; ++mt)
#pragma unroll
                for (int h = 0; h < 2; ++h)
#pragma unroll
                    for (int nb = 0; nb < 4; ++nb) {
                        uint32_t b0 = b_frag[h][nb >> 1][(nb & 1) * 2 + 0];
                        uint32_t b1 = b_frag[h][nb >> 1][(nb & 1) * 2 + 1];
                        mma16816(acc[mt][h][nb], a_frag[mt], b0, b1);
                    }
        }
    }

    const int gr = lane >> 2;
    const int gc = (lane & 3) * 2;
#pragma unroll
    for (int mt = 0; mt < 2; ++mt) {
#pragma unroll
        for (int nb = 0; nb < 4; ++nb) {
            int row0 = by * BM + wm + mt * 16 + gr;
            int col  = bx * 64 + wn + nb * 8 + gc;
            float2 ba = *(const float2*)&bias[col];
            float2 bg = *(const float2*)&bias[Dq + col];
#pragma unroll
            for (int rr = 0; rr < 2; ++rr) {
                int row = row0 + rr * 8;
                float av0 = acc[mt][0][nb][rr * 2 + 0] + ba.x;
                float av1 = acc[mt][0][nb][rr * 2 + 1] + ba.y;
                float gv0 = acc[mt][1][nb][rr * 2 + 0] + bg.x;
                float gv1 = acc[mt][1][nb][rr * 2 + 1] + bg.y;
                float o0 = av0 / (1.0f + __expf(-gv0));
                float o1 = av1 / (1.0f + __expf(-gv1));
                *(__half2*)&YG[(size_t)row * Dq + col] = __floats2half2_rn(o0, o1);
            }
        }
    }
}

// ---------------- launch --------------------------------------------------
extern "C" void kernel_launch(void* const* d_in, const int* in_sizes, int n_in,
                              void* d_out, int out_size) {
    const float* x          = (const float*)d_in[0];
    const float* in_W       = (const float*)d_in[1];
    const float* in_b       = (const float*)d_in[2];
    const float* log_dt     = (const float*)d_in[3];
    const float* Cc         = (const float*)d_in[4];
    const float* log_A_real = (const float*)d_in[5];
    const float* A_imag     = (const float*)d_in[6];
    const float* D_skip     = (const float*)d_in[7];
    const float* glu_W      = (const float*)d_in[8];
    const float* glu_b      = (const float*)d_in[9];
    const float* out_W      = (const float*)d_in[10];
    const float* out_b      = (const float*)d_in[11];
    float* out = (float*)d_out;

    __half *xh, *ut, *yt, *ygh, *wih, *wgh, *woh;
    cudaGetSymbolAddress((void**)&xh,  g_xh);
    cudaGetSymbolAddress((void**)&ut,  g_ut);
    cudaGetSymbolAddress((void**)&yt,  g_yt);
    cudaGetSymbolAddress((void**)&ygh, g_ygh);
    cudaGetSymbolAddress((void**)&wih, g_wih);
    cudaGetSymbolAddress((void**)&wgh, g_wgh);
    cudaGetSymbolAddress((void**)&woh, g_woh);

    const int SMEM_SZ = STAGES * 2 * BM * BK * 2;   // 96KB
    cudaFuncSetAttribute(hgemm_kernel<1>, cudaFuncAttributeMaxDynamicSharedMemorySize, SMEM_SZ);
    cudaFuncSetAttribute(hgemm_kernel<4>, cudaFuncAttributeMaxDynamicSharedMemorySize, SMEM_SZ);
    cudaFuncSetAttribute(hglu_kernel, cudaFuncAttributeMaxDynamicSharedMemorySize, SMEM_SZ);
    cudaFuncSetAttribute(s4chunk_kernel, cudaFuncAttributeMaxDynamicSharedMemorySize, SM_TOTAL_S4);

    // 1) fp16 conversions
    {
        int total4 = N4X + N4I + N4G + N4O;
        cvt_all_kernel<<<(total4 + 255) / 256, 256>>>(x, in_W, glu_W, out_W,
                                                      xh, wih, wgh, woh);
    }

    // 2) in_proj computed transposed: ut[d][m] = in_W @ x^T, written as (B, D, L)
    {
        dim3 grid(Mq / BN, Dq / BM);
        hgemm_kernel<4><<<grid, 256, SMEM_SZ>>>(wih, xh, in_b, nullptr, ut, Dq, Mq, Dq);
    }

    // 3) chunked SSM (prep fused) + skip + GELU -> Yt (B, D, L)
    s4chunk_kernel<<<Dq, 256, SM_TOTAL_S4>>>(ut, log_dt, Cc, log_A_real, A_imag,
                                             D_skip, yt);

    // 4) GLU GEMM (A read transposed from yt) fused with a*sigmoid(g) -> fp16
    {
        dim3 grid(Dq / 64, Mq / BM);
        hglu_kernel<<<grid, 256, SMEM_SZ>>>(yt, wgh, glu_b, ygh, Dq);
    }

    // 5) out_proj + fp32 residual
    {
        dim3 grid(Dq / BN, Mq / BM);
        hgemm_kernel<1><<<grid, 256, SMEM_SZ>>>(ygh, woh, out_b, x, out, Mq, Dq, Dq);
    }
}